// round 14
// baseline (speedup 1.0000x reference)
#include <cuda_runtime.h>
#include <math.h>

// ---------------- problem constants ----------------
#define S_LEN 2048
#define QKV_W 3072
#define DIM_  2048
#define DH_   64
#define KVH_  8
#define HEADS_ 32
#define CDIM_ 1024
#define NC_   128
#define NEGV  (-1e30f)
#define SCALE_ 0.125f
#define PGRID 444   // 3 CTAs/SM * 148 SMs

// ---------------- scratch ----------------
__device__ float g_qkv [S_LEN * QKV_W];
__device__ float g_kbv [2 * KVH_ * NC_ * CDIM_];
__device__ float g_h1  [2 * KVH_ * NC_ * CDIM_];
__device__ float g_body[2 * KVH_ * NC_ * DH_];
__device__ float g_ck  [KVH_ * 129 * DH_];
__device__ float g_cv  [KVH_ * 129 * DH_];
__device__ float g_csim[HEADS_ * S_LEN * 129];
__device__ float g_cout[HEADS_ * S_LEN * DH_];
__device__ float g_fout[HEADS_ * S_LEN * DH_];
__device__ float g_sout[HEADS_ * S_LEN * DH_];
__device__ float g_rq  [HEADS_ * S_LEN * DH_];
__device__ float g_rk  [KVH_  * S_LEN * DH_];
__device__ float g_rcs [S_LEN * 32 * 2];
__device__ int           g_selidx [KVH_ * S_LEN * 8];
__device__ unsigned char g_selmask[KVH_ * S_LEN * 8];
__device__ float g_gate[S_LEN * 96];
// split operand scratch (fragment-interleaved layouts)
__device__ unsigned g_Ahi[DIM_ * S_LEN];
__device__ unsigned g_Alo[DIM_ * S_LEN];
__device__ unsigned g_Bhi[DIM_ * QKV_W];
__device__ unsigned g_Blo[DIM_ * QKV_W];

// permutations: A pairs (m, m+8) adjacent; B quads (n,+8,+16,+24) adjacent
__device__ __forceinline__ int pB_(int n) { return (n & ~31) + ((n & 7) << 2) + ((n >> 3) & 3); }

// ================= split helpers =================
__device__ __forceinline__ unsigned f2tf(float x)
{
    unsigned r;
    asm("cvt.rna.tf32.f32 %0, %1;" : "=r"(r) : "f"(x));
    return r;
}

__device__ __forceinline__ void split_tf(float x, unsigned& hi, unsigned& lo)
{
    hi = f2tf(x);
    lo = f2tf(x - __uint_as_float(hi));
}

__device__ __forceinline__ void mma_tf32(float* c, const unsigned* a, const unsigned* b)
{
    asm volatile(
        "mma.sync.aligned.m16n8k8.row.col.f32.tf32.tf32.f32 "
        "{%0,%1,%2,%3}, {%4,%5,%6,%7}, {%8,%9}, {%0,%1,%2,%3};"
        : "+f"(c[0]), "+f"(c[1]), "+f"(c[2]), "+f"(c[3])
        : "r"(a[0]), "r"(a[1]), "r"(a[2]), "r"(a[3]), "r"(b[0]), "r"(b[1]));
}

__device__ __forceinline__ void cp16(unsigned saddr, const void* g)
{
    asm volatile("cp.async.ca.shared.global [%0], [%1], 16;" :: "r"(saddr), "l"(g));
}

// split + transpose A: float [M][K] -> uint hi/lo [K][pA(M)]
__global__ void split_At(const float* __restrict__ A, int M, int K)
{
    __shared__ float t[32][33];
    const int tid = threadIdx.x;
    const int k0 = blockIdx.x * 32, m0 = blockIdx.y * 32;
    const int c = tid & 31, r = tid >> 5;
#pragma unroll
    for (int i = r; i < 32; i += 8)
        t[i][c] = A[(size_t)(m0 + i) * K + k0 + c];
    __syncthreads();
#pragma unroll
    for (int i = r; i < 32; i += 8) {
        unsigned hi, lo;
        split_tf(t[c][i], hi, lo);
        size_t o = (size_t)(k0 + i) * M + m0 + ((c & 16) + ((c & 7) << 1) + ((c >> 3) & 1));
        g_Ahi[o] = hi;
        g_Alo[o] = lo;
    }
}

// split B (k-major): float [K][N] -> uint hi/lo [K][pB(N)] at offset
__global__ void split_B(const float* __restrict__ B, size_t off, int N, int total)
{
    int idx = blockIdx.x * blockDim.x + threadIdx.x;
    if (idx >= total) return;
    int n = idx % N, k = idx / N;
    unsigned hi, lo;
    split_tf(B[idx], hi, lo);
    size_t o = off + (size_t)k * N + pB_(n);
    g_Bhi[o] = hi;
    g_Blo[o] = lo;
}

// fused gated-combine + split + transpose: writes wout's A operand directly
__global__ void combine_split(void)
{
    __shared__ float t[32][33];
    const int tid = threadIdx.x;
    const int c0 = blockIdx.x * 32;
    const int n0 = blockIdx.y * 32;
    const int c = tid & 31, r = tid >> 5;
    const int hg = c0 >> 6;
#pragma unroll
    for (int i = r; i < 32; i += 8) {
        int n = n0 + i;
        float gg0 = g_gate[n * 96 + hg * 3];
        float gg1 = g_gate[n * 96 + hg * 3 + 1];
        float gg2 = g_gate[n * 96 + hg * 3 + 2];
        size_t src = ((size_t)hg * S_LEN + n) * 64 + ((c0 + c) & 63);
        t[i][c] = gg0 * g_cout[src] + gg1 * g_fout[src] + gg2 * g_sout[src];
    }
    __syncthreads();
#pragma unroll
    for (int i = r; i < 32; i += 8) {
        unsigned hi, lo;
        split_tf(t[c][i], hi, lo);
        size_t o = (size_t)(c0 + i) * DIM_ + n0 + ((c & 16) + ((c & 7) << 1) + ((c >> 3) & 1));
        g_Ahi[o] = hi;
        g_Alo[o] = lo;
    }
}

// ================= 3-product TF32 GEMM, persistent grid-strided ============
// block tile 128x64, warp tile 32x64, 4 warps, 3 CTAs/SM, cp.async x3 stages.
template <int ACT>
__global__ void __launch_bounds__(128, 3)
gemm3p(const float* __restrict__ bias0, const float* __restrict__ bias1,
       float* __restrict__ C, int M, int N, int K,
       int ntiles, int bxdim, int bysplit, size_t boff)
{
    __shared__ __align__(16) unsigned Ah[3][8][136], Al[3][8][136];
    __shared__ __align__(16) unsigned Bh[3][8][72],  Bl[3][8][72];
    const int tid = threadIdx.x;
    const int lane = tid & 31;
    const int wid = tid >> 5;
    const int wm = wid * 32;

    const int ar0 = tid >> 5;
    const int ac0 = (tid & 31) << 2;
    const int ar1 = (tid + 128) >> 5;
    const int brow = tid >> 4;
    const int bc4  = (tid & 15) << 2;

    const unsigned sAh = (unsigned)__cvta_generic_to_shared(&Ah[0][0][0]);
    const unsigned sAl = (unsigned)__cvta_generic_to_shared(&Al[0][0][0]);
    const unsigned sBh = (unsigned)__cvta_generic_to_shared(&Bh[0][0][0]);
    const unsigned sBl = (unsigned)__cvta_generic_to_shared(&Bl[0][0][0]);
    const unsigned aoff0 = (unsigned)(ar0 * 136 + ac0) * 4u;
    const unsigned aoff1 = (unsigned)(ar1 * 136 + ac0) * 4u;
    const unsigned boffs = (unsigned)(brow * 72 + bc4) * 4u;

    const int rr = lane >> 2;
    const int lc = lane & 3;
    const int k0 = lc, k1 = lc + 4;
    const int ktiles = K >> 3;

    for (int tile = blockIdx.x; tile < ntiles; tile += gridDim.x) {
        const int bx = tile % bxdim;
        const int by = tile / bxdim;
        const bool second = (by >= bysplit);
        const size_t bofs = second ? boff : 0;
        const float* bias = second ? bias1 : bias0;
        const size_t abase = (size_t)by * 128;
        const size_t bbase = (size_t)bx * 64;

        __syncthreads();   // protect smem buffers from previous tile

#define ISSUE_(s, kt) do {                                                   \
        size_t a0_ = (size_t)((kt) * 8 + ar0) * M + abase + ac0;             \
        size_t a1_ = (size_t)((kt) * 8 + ar1) * M + abase + ac0;             \
        cp16(sAh + (unsigned)(s) * 4352u + aoff0, g_Ahi + a0_);              \
        cp16(sAh + (unsigned)(s) * 4352u + aoff1, g_Ahi + a1_);              \
        cp16(sAl + (unsigned)(s) * 4352u + aoff0, g_Alo + a0_);              \
        cp16(sAl + (unsigned)(s) * 4352u + aoff1, g_Alo + a1_);              \
        size_t bo_ = bofs + (size_t)((kt) * 8 + brow) * N + bbase + bc4;     \
        cp16(sBh + (unsigned)(s) * 2304u + boffs, g_Bhi + bo_);              \
        cp16(sBl + (unsigned)(s) * 2304u + boffs, g_Blo + bo_);              \
        asm volatile("cp.async.commit_group;" ::: "memory");                 \
    } while (0)

        ISSUE_(0, 0);
        ISSUE_(1, 1);

        float acc[2][8][4];
#pragma unroll
        for (int mf = 0; mf < 2; ++mf)
#pragma unroll
            for (int nf = 0; nf < 8; ++nf)
#pragma unroll
                for (int i = 0; i < 4; ++i) acc[mf][nf][i] = 0.f;

        int cur = 0;
        for (int kt = 0; kt < ktiles; ++kt) {
            asm volatile("cp.async.wait_group 1;" ::: "memory");
            __syncthreads();

            const unsigned* pAh = &Ah[cur][0][0];
            const unsigned* pAl = &Al[cur][0][0];
            const unsigned* pBh = &Bh[cur][0][0];
            const unsigned* pBl = &Bl[cur][0][0];
            const int wa0 = k0 * 136 + wm + 2 * rr;
            const int wa1 = k1 * 136 + wm + 2 * rr;
            const int wb0 = k0 * 72 + 4 * rr;
            const int wb1 = k1 * 72 + 4 * rr;

            unsigned bh[8][2], bl[8][2];
            {
                uint4 h0 = *(const uint4*)(pBh + wb0);
                uint4 h1 = *(const uint4*)(pBh + wb1);
                uint4 h2 = *(const uint4*)(pBh + wb0 + 32);
                uint4 h3 = *(const uint4*)(pBh + wb1 + 32);
                uint4 l0 = *(const uint4*)(pBl + wb0);
                uint4 l1 = *(const uint4*)(pBl + wb1);
                uint4 l2 = *(const uint4*)(pBl + wb0 + 32);
                uint4 l3 = *(const uint4*)(pBl + wb1 + 32);
                bh[0][0] = h0.x; bh[1][0] = h0.y; bh[2][0] = h0.z; bh[3][0] = h0.w;
                bh[0][1] = h1.x; bh[1][1] = h1.y; bh[2][1] = h1.z; bh[3][1] = h1.w;
                bh[4][0] = h2.x; bh[5][0] = h2.y; bh[6][0] = h2.z; bh[7][0] = h2.w;
                bh[4][1] = h3.x; bh[5][1] = h3.y; bh[6][1] = h3.z; bh[7][1] = h3.w;
                bl[0][0] = l0.x; bl[1][0] = l0.y; bl[2][0] = l0.z; bl[3][0] = l0.w;
                bl[0][1] = l1.x; bl[1][1] = l1.y; bl[2][1] = l1.z; bl[3][1] = l1.w;
                bl[4][0] = l2.x; bl[5][0] = l2.y; bl[6][0] = l2.z; bl[7][0] = l2.w;
                bl[4][1] = l3.x; bl[5][1] = l3.y; bl[6][1] = l3.z; bl[7][1] = l3.w;
            }
            unsigned ah[2][4], al[2][4];
#pragma unroll
            for (int mf = 0; mf < 2; ++mf) {
                uint2 h0 = *(const uint2*)(pAh + wa0 + mf * 16);
                uint2 h1 = *(const uint2*)(pAh + wa1 + mf * 16);
                uint2 l0 = *(const uint2*)(pAl + wa0 + mf * 16);
                uint2 l1 = *(const uint2*)(pAl + wa1 + mf * 16);
                ah[mf][0] = h0.x; ah[mf][1] = h0.y; ah[mf][2] = h1.x; ah[mf][3] = h1.y;
                al[mf][0] = l0.x; al[mf][1] = l0.y; al[mf][2] = l1.x; al[mf][3] = l1.y;
            }
            // product-major issue; per-acc order (al*bh, ah*bl, ah*bh) unchanged.
#pragma unroll
            for (int mf = 0; mf < 2; ++mf)
#pragma unroll
                for (int nf = 0; nf < 8; ++nf)
                    mma_tf32(acc[mf][nf], al[mf], bh[nf]);
#pragma unroll
            for (int mf = 0; mf < 2; ++mf)
#pragma unroll
                for (int nf = 0; nf < 8; ++nf)
                    mma_tf32(acc[mf][nf], ah[mf], bl[nf]);
#pragma unroll
            for (int mf = 0; mf < 2; ++mf)
#pragma unroll
                for (int nf = 0; nf < 8; ++nf)
                    mma_tf32(acc[mf][nf], ah[mf], bh[nf]);

            if (kt + 2 < ktiles) {
                int s = (cur + 2) % 3;
                ISSUE_(s, kt + 2);
            } else {
                asm volatile("cp.async.commit_group;" ::: "memory");
            }
            cur = (cur + 1) % 3;
        }
#undef ISSUE_

        const int cc2 = lc * 2;
#pragma unroll
        for (int mf = 0; mf < 2; ++mf) {
            const int r0 = by * 128 + wm + mf * 16 + rr;
#pragma unroll
            for (int nf = 0; nf < 8; ++nf) {
                const int col = bx * 64 + nf * 8 + cc2;
                float b0 = bias ? bias[col] : 0.f;
                float b1 = bias ? bias[col + 1] : 0.f;
                float v0 = acc[mf][nf][0] + b0, v1 = acc[mf][nf][1] + b1;
                float v2 = acc[mf][nf][2] + b0, v3 = acc[mf][nf][3] + b1;
                if (ACT == 1) {
                    v0 = fmaxf(v0, 0.f); v1 = fmaxf(v1, 0.f);
                    v2 = fmaxf(v2, 0.f); v3 = fmaxf(v3, 0.f);
                }
                float2 w0 = {v0, v1}, w1 = {v2, v3};
                *(float2*)(C + (size_t)r0 * N + col) = w0;
                *(float2*)(C + (size_t)(r0 + 8) * N + col) = w1;
            }
        }
    }
}

// ================= skinny GEMM with row-split B select ==========
template <int ACT, int NCOL, int NSL, int RPB>
__global__ void skinny_gemm(const float* __restrict__ A, const float* __restrict__ B,
                            const float* __restrict__ B2, const float* __restrict__ bias,
                            const float* __restrict__ bias2, float* __restrict__ C,
                            int N, int K, int rowsplit)
{
    __shared__ float sA[RPB][128];
    __shared__ float sred[NSL][RPB][NCOL];
    const int tid = threadIdx.x;
    const int row0 = blockIdx.x * RPB;
    if (row0 >= rowsplit) { B = B2; bias = bias2; }
    const int c = tid % NCOL, sl = tid / NCOL;
    const bool active = sl < NSL;
    const int kper = 128 / NSL;
    float acc[RPB];
#pragma unroll
    for (int r = 0; r < RPB; ++r) acc[r] = 0.f;

    for (int k0 = 0; k0 < K; k0 += 128) {
        __syncthreads();
        for (int i = tid; i < RPB * 128; i += 256) {
            int r = i >> 7, kk = i & 127;
            sA[r][kk] = A[(size_t)(row0 + r) * K + k0 + kk];
        }
        __syncthreads();
        if (active) {
            for (int kk = sl * kper; kk < (sl + 1) * kper; ++kk) {
                float b = B[(size_t)(k0 + kk) * N + c];
#pragma unroll
                for (int r = 0; r < RPB; ++r) acc[r] = fmaf(sA[r][kk], b, acc[r]);
            }
        }
    }
    if (active) {
#pragma unroll
        for (int r = 0; r < RPB; ++r) sred[sl][r][c] = acc[r];
    }
    __syncthreads();
    for (int i = tid; i < RPB * NCOL; i += 256) {
        int r = i / NCOL, cc = i % NCOL;
        float s = 0.f;
#pragma unroll
        for (int q = 0; q < NSL; ++q) s += sred[q][r][cc];
        if (bias) s += bias[cc];
        if (ACT == 2) s = 1.f / (1.f + expf(-s));
        C[(size_t)(row0 + r) * N + cc] = s;
    }
}

// ---------------- kb/vb construction ----------------
__global__ void build_kb_vb(const float* __restrict__ k_pos, const float* __restrict__ v_pos)
{
    int idx = blockIdx.x * blockDim.x + threadIdx.x;
    if (idx >= KVH_ * NC_ * CDIM_) return;
    int d = idx & 63;
    int i = (idx >> 6) & 15;
    int c = (idx >> 10) & 127;
    int h = idx >> 17;
    int t = c * 16 + i;
    float kv = g_qkv[(size_t)t * QKV_W + DIM_ + h * DH_ + d];
    float vv = g_qkv[(size_t)t * QKV_W + DIM_ + 512 + h * DH_ + d];
    g_kbv[idx]                      = kv + k_pos[(h * 16 + i) * 64 + d];
    g_kbv[idx + KVH_ * NC_ * CDIM_] = vv + v_pos[(h * 16 + i) * 64 + d];
}

// ---------------- assemble ck/cv ----------------
__global__ void assemble_c(const float* __restrict__ mem, float* __restrict__ dst,
                           const float* __restrict__ body)
{
    int idx = blockIdx.x * blockDim.x + threadIdx.x;
    if (idx >= KVH_ * 129 * DH_) return;
    int d = idx % 64;
    int j = (idx / 64) % 129;
    int h = idx / (64 * 129);
    dst[idx] = (j == 0) ? mem[h * 64 + d] : body[((h * NC_) + (j - 1)) * 64 + d];
}

// ---------------- compression attention: warp per (h,n), 4 g-heads --------
__global__ void csoft_kernel()
{
    __shared__ float sp[8][4][132];
    int gw = (blockIdx.x * blockDim.x + threadIdx.x) >> 5;
    int lane = threadIdx.x & 31, wl = (threadIdx.x >> 5) & 7;
    if (gw >= KVH_ * S_LEN) return;
    int h = gw >> 11, n = gw & (S_LEN - 1);
    const float* qb = g_qkv + (size_t)n * QKV_W + h * 4 * DH_;
    float q0[4], q1[4];
#pragma unroll
    for (int g = 0; g < 4; ++g) { q0[g] = qb[g * 64 + lane]; q1[g] = qb[g * 64 + lane + 32]; }
    const float* ckh = g_ck + h * 129 * 64;
    const int nvalid = (n >> 4) + 1;

    float m[4] = {-1e38f, -1e38f, -1e38f, -1e38f};
    for (int j = 0; j < nvalid; ++j) {
        const float* kr = ckh + j * 64;
        float k0 = kr[lane], k1 = kr[lane + 32];
#pragma unroll
        for (int g = 0; g < 4; ++g) {
            float s = q0[g] * k0 + q1[g] * k1;
#pragma unroll
            for (int o = 16; o; o >>= 1) s += __shfl_xor_sync(0xffffffffu, s, o);
            s *= SCALE_;
            if (lane == 0) sp[wl][g][j] = s;
            m[g] = fmaxf(m[g], s);
        }
    }
    __syncwarp();
#pragma unroll
    for (int g = 0; g < 4; ++g) {
        float* out = g_csim + (((size_t)(h * 4 + g) * S_LEN) + n) * 129;
        for (int j = lane; j < 129; j += 32) out[j] = (j < nvalid) ? sp[wl][g][j] : NEGV;
    }
    float sum[4] = {0.f, 0.f, 0.f, 0.f};
    for (int j = lane; j < nvalid; j += 32) {
#pragma unroll
        for (int g = 0; g < 4; ++g) {
            float e = expf(sp[wl][g][j] - m[g]);
            sp[wl][g][j] = e;
            sum[g] += e;
        }
    }
#pragma unroll
    for (int g = 0; g < 4; ++g)
#pragma unroll
        for (int o = 16; o; o >>= 1) sum[g] += __shfl_xor_sync(0xffffffffu, sum[g], o);
    __syncwarp();
    const float* cvh = g_cv + h * 129 * 64;
    float a0[4] = {0.f, 0.f, 0.f, 0.f}, a1[4] = {0.f, 0.f, 0.f, 0.f};
    for (int j = 0; j < nvalid; ++j) {
        float v0 = cvh[j * 64 + lane], v1 = cvh[j * 64 + lane + 32];
#pragma unroll
        for (int g = 0; g < 4; ++g) {
            float p = sp[wl][g][j];
            a0[g] = fmaf(p, v0, a0[g]);
            a1[g] = fmaf(p, v1, a1[g]);
        }
    }
#pragma unroll
    for (int g = 0; g < 4; ++g) {
        float inv = 1.f / sum[g];
        size_t o = (((size_t)(h * 4 + g) * S_LEN) + n) * 64;
        g_cout[o + lane]      = a0[g] * inv;
        g_cout[o + lane + 32] = a1[g] * inv;
    }
}

// ---------------- importance + top-8 selection ----------------
__global__ void topk_kernel()
{
    int w = (blockIdx.x * blockDim.x + threadIdx.x) >> 5;
    int lane = threadIdx.x & 31;
    if (w >= KVH_ * S_LEN) return;
    int h = w >> 11, n = w & (S_LEN - 1);
    float vals[4];
    int js[4];
#pragma unroll
    for (int r = 0; r < 4; ++r) {
        int jj = lane + r * 32;
        float s = 0.f;
        for (int g = 0; g < 4; ++g)
            s += g_csim[(((size_t)(h * 4 + g) * S_LEN + n) * 129) + jj + 1];
        vals[r] = s * 0.25f;
        js[r] = jj;
    }
    float m = -1000.f;
#pragma unroll
    for (int r = 0; r < 4; ++r) m = fmaxf(m, vals[r]);
#pragma unroll
    for (int o = 16; o; o >>= 1) m = fmaxf(m, __shfl_xor_sync(0xffffffffu, m, o));
    float sum = 0.f;
#pragma unroll
    for (int r = 0; r < 4; ++r) sum += expf(vals[r] - m);
#pragma unroll
    for (int o = 16; o; o >>= 1) sum += __shfl_xor_sync(0xffffffffu, sum, o);
    sum += expf(-1000.f - m);
    for (int t = 0; t < 8; ++t) {
        float bv = vals[0]; int bj = js[0];
#pragma unroll
        for (int r = 1; r < 4; ++r)
            if (vals[r] > bv || (vals[r] == bv && js[r] < bj)) { bv = vals[r]; bj = js[r]; }
        float v = bv; int j = bj;
#pragma unroll
        for (int o = 16; o; o >>= 1) {
            float vo = __shfl_xor_sync(0xffffffffu, v, o);
            int   jo = __shfl_xor_sync(0xffffffffu, j, o);
            if (vo > v || (vo == v && jo < j)) { v = vo; j = jo; }
        }
        if (lane == 0) {
            g_selidx[w * 8 + t] = j;
            float p = expf(v - m) / sum;
            g_selmask[w * 8 + t] = (p > 1e-10f) ? 1 : 0;
        }
        int owner = j & 31, rr = j >> 5;
        if (lane == owner) vals[rr] = -INFINITY;
    }
}

// ---------------- RoPE ----------------
__global__ void rope_table()
{
    int idx = blockIdx.x * blockDim.x + threadIdx.x;
    if (idx >= S_LEN * 32) return;
    int p = idx & 31;
    int n = idx >> 5;
    double inv = pow(10000.0, -((double)(2 * p)) / 64.0);
    double a = (double)n * inv;
    g_rcs[idx * 2]     = (float)cos(a);
    g_rcs[idx * 2 + 1] = (float)sin(a);
}

__global__ void rope_apply()
{
    int idx = blockIdx.x * blockDim.x + threadIdx.x;
    if (idx >= 40 * S_LEN * 32) return;
    int p = idx & 31;
    int n = (idx >> 5) & (S_LEN - 1);
    int hh = idx >> 16;
    float c = g_rcs[(n * 32 + p) * 2];
    float s = g_rcs[(n * 32 + p) * 2 + 1];
    const float* src; float* dst;
    if (hh < 32) {
        src = g_qkv + (size_t)n * QKV_W + hh * DH_;
        dst = g_rq + ((size_t)hh * S_LEN + n) * DH_;
    } else {
        int h = hh - 32;
        src = g_qkv + (size_t)n * QKV_W + DIM_ + h * DH_;
        dst = g_rk + ((size_t)h * S_LEN + n) * DH_;
    }
    float x1 = src[2 * p], x2 = src[2 * p + 1];
    dst[2 * p]     = x1 * c - x2 * s;
    dst[2 * p + 1] = x1 * s + x2 * c;
}

// ---------------- fine attention: warp per (h,n), 4 g-heads ----------------
__global__ void fine_kernel()
{
    __shared__ float sp[8][4][144];
    int gw = (blockIdx.x * blockDim.x + threadIdx.x) >> 5;
    int lane = threadIdx.x & 31, wl = (threadIdx.x >> 5) & 7;
    if (gw >= KVH_ * S_LEN) return;
    int h = gw >> 11, n = gw & (S_LEN - 1);
    float q0[4], q1[4];
#pragma unroll
    for (int g = 0; g < 4; ++g) {
        const float* q = g_rq + (((size_t)(h * 4 + g) * S_LEN) + n) * 64;
        q0[g] = q[lane]; q1[g] = q[lane + 32];
    }
    const int base = (h * S_LEN + n) * 8;
    const int ownb = n >> 4;

    float m[4] = {-1e38f, -1e38f, -1e38f, -1e38f};
    for (int j = 0; j < 144; ++j) {
        int bsel = j >> 4, off = j & 15;
        int blk; bool valid;
        if (bsel < 8) { blk = g_selidx[base + bsel]; valid = g_selmask[base + bsel] != 0; }
        else          { blk = ownb;                  valid = (n & 15) >= off; }
        float k0 = 0.f, k1 = 0.f;
        if (valid) {
            const float* kr = g_rk + ((size_t)h * S_LEN + blk * 16 + off) * 64;
            k0 = kr[lane]; k1 = kr[lane + 32];
        }
#pragma unroll
        for (int g = 0; g < 4; ++g) {
            float s = NEGV;
            if (valid) {
                float t = q0[g] * k0 + q1[g] * k1;
#pragma unroll
                for (int o = 16; o; o >>= 1) t += __shfl_xor_sync(0xffffffffu, t, o);
                s = t * SCALE_;
            }
            if (lane == 0) sp[wl][g][j] = s;
            m[g] = fmaxf(m[g], s);
        }
    }
    __syncwarp();
    float sum[4] = {0.f, 0.f, 0.f, 0.f};
    for (int j = lane; j < 144; j += 32) {
#pragma unroll
        for (int g = 0; g < 4; ++g) {
            float e = expf(sp[wl][g][j] - m[g]);
            sp[wl][g][j] = e;
            sum[g] += e;
        }
    }
#pragma unroll
    for (int g = 0; g < 4; ++g)
#pragma unroll
        for (int o = 16; o; o >>= 1) sum[g] += __shfl_xor_sync(0xffffffffu, sum[g], o);
    __syncwarp();
    float a0[4] = {0.f, 0.f, 0.f, 0.f}, a1[4] = {0.f, 0.f, 0.f, 0.f};
    for (int j = 0; j < 144; ++j) {
        int bsel = j >> 4, off = j & 15;
        int blk = (bsel < 8) ? g_selidx[base + bsel] : ownb;
        int t = blk * 16 + off;
        const float* vr = g_qkv + (size_t)t * QKV_W + DIM_ + 512 + h * DH_;
        float v0 = vr[lane], v1 = vr[lane + 32];
#pragma unroll
        for (int g = 0; g < 4; ++g) {
            float p = sp[wl][g][j];
            a0[g] = fmaf(p, v0, a0[g]);
            a1[g] = fmaf(p, v1, a1[g]);
        }
    }
#pragma unroll
    for (int g = 0; g < 4; ++g) {
        float inv = 1.f / sum[g];
        size_t o = (((size_t)(h * 4 + g) * S_LEN) + n) * 64;
        g_fout[o + lane]      = a0[g] * inv;
        g_fout[o + lane + 32] = a1[g] * inv;
    }
}

// ---------------- sliding-window attention: warp per (h,n), 4 g-heads -----
__global__ void slide_kernel()
{
    __shared__ float sp[8][4][66];
    int gw = (blockIdx.x * blockDim.x + threadIdx.x) >> 5;
    int lane = threadIdx.x & 31, wl = (threadIdx.x >> 5) & 7;
    if (gw >= KVH_ * S_LEN) return;
    int h = gw >> 11, n = gw & (S_LEN - 1);
    float q0[4], q1[4];
#pragma unroll
    for (int g = 0; g < 4; ++g) {
        const float* q = g_rq + (((size_t)(h * 4 + g) * S_LEN) + n) * 64;
        q0[g] = q[lane]; q1[g] = q[lane + 32];
    }
    int lo = n - 64; if (lo < 0) lo = 0;
    int cnt = n - lo + 1;

    float m[4] = {-1e38f, -1e38f, -1e38f, -1e38f};
    for (int jj = 0; jj < cnt; ++jj) {
        const float* kr = g_rk + ((size_t)h * S_LEN + lo + jj) * 64;
        float k0 = kr[lane], k1 = kr[lane + 32];
#pragma unroll
        for (int g = 0; g < 4; ++g) {
            float t = q0[g] * k0 + q1[g] * k1;
#pragma unroll
            for (int o = 16; o; o >>= 1) t += __shfl_xor_sync(0xffffffffu, t, o);
            float s = t * SCALE_;
            if (lane == 0) sp[wl][g][jj] = s;
            m[g] = fmaxf(m[g], s);
        }
    }
    __syncwarp();
    float sum[4] = {0.f, 0.f, 0.f, 0.f};
    for (int jj = lane; jj < cnt; jj += 32) {
#pragma unroll
        for (int g = 0; g < 4; ++g) {
            float e = expf(sp[wl][g][jj] - m[g]);
            sp[wl][g][jj] = e;
            sum[g] += e;
        }
    }
#pragma unroll
    for (int g = 0; g < 4; ++g)
#pragma unroll
        for (int o = 16; o; o >>= 1) sum[g] += __shfl_xor_sync(0xffffffffu, sum[g], o);
    __syncwarp();
    float a0[4] = {0.f, 0.f, 0.f, 0.f}, a1[4] = {0.f, 0.f, 0.f, 0.f};
    for (int jj = 0; jj < cnt; ++jj) {
        const float* vr = g_qkv + (size_t)(lo + jj) * QKV_W + DIM_ + 512 + h * DH_;
        float v0 = vr[lane], v1 = vr[lane + 32];
#pragma unroll
        for (int g = 0; g < 4; ++g) {
            float p = sp[wl][g][jj];
            a0[g] = fmaf(p, v0, a0[g]);
            a1[g] = fmaf(p, v1, a1[g]);
        }
    }
#pragma unroll
    for (int g = 0; g < 4; ++g) {
        float inv = 1.f / sum[g];
        size_t o = (((size_t)(h * 4 + g) * S_LEN) + n) * 64;
        g_sout[o + lane]      = a0[g] * inv;
        g_sout[o + lane + 32] = a1[g] * inv;
    }
}

// ---------------- launcher ----------------
extern "C" void kernel_launch(void* const* d_in, const int* in_sizes, int n_in,
                              void* d_out, int out_size)
{
    const float* x      = (const float*)d_in[0];
    const float* w_qkv  = (const float*)d_in[1];
    const float* k_pos  = (const float*)d_in[2];
    const float* v_pos  = (const float*)d_in[3];
    const float* k_cw1  = (const float*)d_in[4];
    const float* k_cb1  = (const float*)d_in[5];
    const float* k_cw2  = (const float*)d_in[6];
    const float* k_cb2  = (const float*)d_in[7];
    const float* v_cw1  = (const float*)d_in[8];
    const float* v_cb1  = (const float*)d_in[9];
    const float* v_cw2  = (const float*)d_in[10];
    const float* v_cb2  = (const float*)d_in[11];
    const float* mem_ck = (const float*)d_in[12];
    const float* mem_cv = (const float*)d_in[13];
    const float* w_gate = (const float*)d_in[14];
    const float* b_gate = (const float*)d_in[15];
    const float* w_out  = (const float*)d_in[16];
    float* out = (float*)d_out;

    float *qkv, *kbv, *h1, *body, *gate, *ck, *cv;
    cudaGetSymbolAddress((void**)&qkv,  g_qkv);
    cudaGetSymbolAddress((void**)&kbv,  g_kbv);
    cudaGetSymbolAddress((void**)&h1,   g_h1);
    cudaGetSymbolAddress((void**)&body, g_body);
    cudaGetSymbolAddress((void**)&gate, g_gate);
    cudaGetSymbolAddress((void**)&ck,   g_ck);
    cudaGetSymbolAddress((void**)&cv,   g_cv);

    const int NOSPLIT = 1 << 30;

    // launch #1: rope table (no deps) — keeps qkv gemm3p at launch #4 for ncu
    rope_table<<<(S_LEN * 32) / 256, 256>>>();
    // 1) qkv projection: 768 tiles (48 x 16), persistent grid
    split_At<<<dim3(DIM_ / 32, S_LEN / 32), 256>>>(x, S_LEN, DIM_);
    split_B<<<(DIM_ * QKV_W) / 256, 256>>>(w_qkv, 0, QKV_W, DIM_ * QKV_W);
    gemm3p<0><<<PGRID, 128>>>(nullptr, nullptr, qkv, S_LEN, QKV_W, DIM_,
                              768, QKV_W / 64, NOSPLIT, 0);
    // 2) compression inputs (merged k/v)
    build_kb_vb<<<(KVH_ * NC_ * CDIM_) / 256, 256>>>(k_pos, v_pos);
    // 3) merged K+V compression MLP layer 1: 256 tiles (16 x 16)
    split_At<<<dim3(CDIM_ / 32, 2048 / 32), 256>>>(kbv, 2048, CDIM_);
    split_B<<<(CDIM_ * CDIM_) / 256, 256>>>(k_cw1, 0, CDIM_, CDIM_ * CDIM_);
    split_B<<<(CDIM_ * CDIM_) / 256, 256>>>(v_cw1, (size_t)CDIM_ * CDIM_, CDIM_, CDIM_ * CDIM_);
    gemm3p<1><<<256, 128>>>(k_cb1, v_cb1, h1, 2048, CDIM_, CDIM_,
                            256, 16, 8, (size_t)CDIM_ * CDIM_);
    // layer 2 (merged skinny)
    skinny_gemm<0, 64, 4, 4><<<512, 256>>>(h1, k_cw2, v_cw2, k_cb2, v_cb2, body,
                                           64, CDIM_, 1024);
    assemble_c<<<(KVH_ * 129 * DH_ + 255) / 256, 256>>>(mem_ck, ck, body);
    assemble_c<<<(KVH_ * 129 * DH_ + 255) / 256, 256>>>(mem_cv, cv, body + 1024 * 64);
    // 5) compression attention (4 g-heads per warp) + top-k
    csoft_kernel<<<KVH_ * S_LEN / 8, 256>>>();
    topk_kernel<<<KVH_ * S_LEN / 8, 256>>>();
    // 6) RoPE apply
    rope_apply<<<(40 * S_LEN * 32) / 256, 256>>>();
    // 7) fine + sliding attention (4 g-heads per warp)
    fine_kernel<<<KVH_ * S_LEN / 8, 256>>>();
    slide_kernel<<<KVH_ * S_LEN / 8, 256>>>();
    // 8) gates
    skinny_gemm<2, 96, 2, 4><<<512, 256>>>(x, w_gate, w_gate, b_gate, b_gate, gate,
                                           96, DIM_, NOSPLIT);
    // 9) fused combine+split, then output projection: 512 tiles (32 x 16)
    combine_split<<<dim3(DIM_ / 32, S_LEN / 32), 256>>>();
    split_B<<<(DIM_ * DIM_) / 256, 256>>>(w_out, 0, DIM_, DIM_ * DIM_);
    gemm3p<0><<<PGRID, 128>>>(nullptr, nullptr, out, S_LEN, DIM_, DIM_,
                              512, DIM_ / 64, NOSPLIT, 0);
}

// round 15
// speedup vs baseline: 1.0642x; 1.0642x over previous
#include <cuda_runtime.h>
#include <math.h>

// ---------------- problem constants ----------------
#define S_LEN 2048
#define QKV_W 3072
#define DIM_  2048
#define DH_   64
#define KVH_  8
#define HEADS_ 32
#define CDIM_ 1024
#define NC_   128
#define NEGV  (-1e30f)
#define SCALE_ 0.125f
#define PGRID 444

// ---------------- scratch ----------------
__device__ float g_qkv [S_LEN * QKV_W];
__device__ float g_kbv [2 * KVH_ * NC_ * CDIM_];
__device__ float g_h1  [2 * KVH_ * NC_ * CDIM_];
__device__ float g_body[2 * KVH_ * NC_ * DH_];
__device__ float g_ck  [KVH_ * 129 * DH_];
__device__ float g_cv  [KVH_ * 129 * DH_];
__device__ float g_csim[HEADS_ * S_LEN * 129];
__device__ float g_cout[HEADS_ * S_LEN * DH_];
__device__ float g_fout[HEADS_ * S_LEN * DH_];
__device__ float g_sout[HEADS_ * S_LEN * DH_];
__device__ float g_rq  [HEADS_ * S_LEN * DH_];
__device__ float g_rk  [KVH_  * S_LEN * DH_];
__device__ float g_rcs [S_LEN * 32 * 2];
__device__ int           g_selidx [KVH_ * S_LEN * 8];
__device__ unsigned char g_selmask[KVH_ * S_LEN * 8];
__device__ float g_gate[S_LEN * 96];
// split operand scratch (fragment-interleaved layouts)
__device__ unsigned g_Ahi[DIM_ * S_LEN];
__device__ unsigned g_Alo[DIM_ * S_LEN];
__device__ unsigned g_Bhi[DIM_ * QKV_W];
__device__ unsigned g_Blo[DIM_ * QKV_W];

__device__ __forceinline__ int pB_(int n) { return (n & ~31) + ((n & 7) << 2) + ((n >> 3) & 3); }

// ================= split helpers =================
__device__ __forceinline__ unsigned f2tf(float x)
{
    unsigned r;
    asm("cvt.rna.tf32.f32 %0, %1;" : "=r"(r) : "f"(x));
    return r;
}

__device__ __forceinline__ void split_tf(float x, unsigned& hi, unsigned& lo)
{
    hi = f2tf(x);
    lo = f2tf(x - __uint_as_float(hi));
}

__device__ __forceinline__ void mma_tf32(float* c, const unsigned* a, const unsigned* b)
{
    asm volatile(
        "mma.sync.aligned.m16n8k8.row.col.f32.tf32.tf32.f32 "
        "{%0,%1,%2,%3}, {%4,%5,%6,%7}, {%8,%9}, {%0,%1,%2,%3};"
        : "+f"(c[0]), "+f"(c[1]), "+f"(c[2]), "+f"(c[3])
        : "r"(a[0]), "r"(a[1]), "r"(a[2]), "r"(a[3]), "r"(b[0]), "r"(b[1]));
}

__device__ __forceinline__ void cp16(unsigned saddr, const void* g)
{
    asm volatile("cp.async.ca.shared.global [%0], [%1], 16;" :: "r"(saddr), "l"(g));
}

// split + transpose A
__global__ void split_At(const float* __restrict__ A, int M, int K)
{
    __shared__ float t[32][33];
    const int tid = threadIdx.x;
    const int k0 = blockIdx.x * 32, m0 = blockIdx.y * 32;
    const int c = tid & 31, r = tid >> 5;
#pragma unroll
    for (int i = r; i < 32; i += 8)
        t[i][c] = A[(size_t)(m0 + i) * K + k0 + c];
    __syncthreads();
#pragma unroll
    for (int i = r; i < 32; i += 8) {
        unsigned hi, lo;
        split_tf(t[c][i], hi, lo);
        size_t o = (size_t)(k0 + i) * M + m0 + ((c & 16) + ((c & 7) << 1) + ((c >> 3) & 1));
        g_Ahi[o] = hi;
        g_Alo[o] = lo;
    }
}

// split B
__global__ void split_B(const float* __restrict__ B, size_t off, int N, int total)
{
    int idx = blockIdx.x * blockDim.x + threadIdx.x;
    if (idx >= total) return;
    int n = idx % N, k = idx / N;
    unsigned hi, lo;
    split_tf(B[idx], hi, lo);
    size_t o = off + (size_t)k * N + pB_(n);
    g_Bhi[o] = hi;
    g_Blo[o] = lo;
}

// fused gated-combine + split + transpose
__global__ void combine_split(void)
{
    __shared__ float t[32][33];
    const int tid = threadIdx.x;
    const int c0 = blockIdx.x * 32;
    const int n0 = blockIdx.y * 32;
    const int c = tid & 31, r = tid >> 5;
    const int hg = c0 >> 6;
#pragma unroll
    for (int i = r; i < 32; i += 8) {
        int n = n0 + i;
        float gg0 = g_gate[n * 96 + hg * 3];
        float gg1 = g_gate[n * 96 + hg * 3 + 1];
        float gg2 = g_gate[n * 96 + hg * 3 + 2];
        size_t src = ((size_t)hg * S_LEN + n) * 64 + ((c0 + c) & 63);
        t[i][c] = gg0 * g_cout[src] + gg1 * g_fout[src] + gg2 * g_sout[src];
    }
    __syncthreads();
#pragma unroll
    for (int i = r; i < 32; i += 8) {
        unsigned hi, lo;
        split_tf(t[c][i], hi, lo);
        size_t o = (size_t)(c0 + i) * DIM_ + n0 + ((c & 16) + ((c & 7) << 1) + ((c >> 3) & 1));
        g_Ahi[o] = hi;
        g_Alo[o] = lo;
    }
}

// ================= 3-product TF32 GEMM, persistent grid-strided ============
template <int ACT>
__global__ void __launch_bounds__(128, 3)
gemm3p(const float* __restrict__ bias0, const float* __restrict__ bias1,
       float* __restrict__ C, int M, int N, int K,
       int ntiles, int bxdim, int bysplit, size_t boff)
{
    __shared__ __align__(16) unsigned Ah[3][8][136], Al[3][8][136];
    __shared__ __align__(16) unsigned Bh[3][8][72],  Bl[3][8][72];
    const int tid = threadIdx.x;
    const int lane = tid & 31;
    const int wid = tid >> 5;
    const int wm = wid * 32;

    const int ar0 = tid >> 5;
    const int ac0 = (tid & 31) << 2;
    const int ar1 = (tid + 128) >> 5;
    const int brow = tid >> 4;
    const int bc4  = (tid & 15) << 2;

    const unsigned sAh = (unsigned)__cvta_generic_to_shared(&Ah[0][0][0]);
    const unsigned sAl = (unsigned)__cvta_generic_to_shared(&Al[0][0][0]);
    const unsigned sBh = (unsigned)__cvta_generic_to_shared(&Bh[0][0][0]);
    const unsigned sBl = (unsigned)__cvta_generic_to_shared(&Bl[0][0][0]);
    const unsigned aoff0 = (unsigned)(ar0 * 136 + ac0) * 4u;
    const unsigned aoff1 = (unsigned)(ar1 * 136 + ac0) * 4u;
    const unsigned boffs = (unsigned)(brow * 72 + bc4) * 4u;

    const int rr = lane >> 2;
    const int lc = lane & 3;
    const int k0 = lc, k1 = lc + 4;
    const int ktiles = K >> 3;

    for (int tile = blockIdx.x; tile < ntiles; tile += gridDim.x) {
        const int bx = tile % bxdim;
        const int by = tile / bxdim;
        const bool second = (by >= bysplit);
        const size_t bofs = second ? boff : 0;
        const float* bias = second ? bias1 : bias0;
        const size_t abase = (size_t)by * 128;
        const size_t bbase = (size_t)bx * 64;

        __syncthreads();

#define ISSUE_(s, kt) do {                                                   \
        size_t a0_ = (size_t)((kt) * 8 + ar0) * M + abase + ac0;             \
        size_t a1_ = (size_t)((kt) * 8 + ar1) * M + abase + ac0;             \
        cp16(sAh + (unsigned)(s) * 4352u + aoff0, g_Ahi + a0_);              \
        cp16(sAh + (unsigned)(s) * 4352u + aoff1, g_Ahi + a1_);              \
        cp16(sAl + (unsigned)(s) * 4352u + aoff0, g_Alo + a0_);              \
        cp16(sAl + (unsigned)(s) * 4352u + aoff1, g_Alo + a1_);              \
        size_t bo_ = bofs + (size_t)((kt) * 8 + brow) * N + bbase + bc4;     \
        cp16(sBh + (unsigned)(s) * 2304u + boffs, g_Bhi + bo_);              \
        cp16(sBl + (unsigned)(s) * 2304u + boffs, g_Blo + bo_);              \
        asm volatile("cp.async.commit_group;" ::: "memory");                 \
    } while (0)

        ISSUE_(0, 0);
        ISSUE_(1, 1);

        float acc[2][8][4];
#pragma unroll
        for (int mf = 0; mf < 2; ++mf)
#pragma unroll
            for (int nf = 0; nf < 8; ++nf)
#pragma unroll
                for (int i = 0; i < 4; ++i) acc[mf][nf][i] = 0.f;

        int cur = 0;
        for (int kt = 0; kt < ktiles; ++kt) {
            asm volatile("cp.async.wait_group 1;" ::: "memory");
            __syncthreads();

            const unsigned* pAh = &Ah[cur][0][0];
            const unsigned* pAl = &Al[cur][0][0];
            const unsigned* pBh = &Bh[cur][0][0];
            const unsigned* pBl = &Bl[cur][0][0];
            const int wa0 = k0 * 136 + wm + 2 * rr;
            const int wa1 = k1 * 136 + wm + 2 * rr;
            const int wb0 = k0 * 72 + 4 * rr;
            const int wb1 = k1 * 72 + 4 * rr;

            unsigned bh[8][2], bl[8][2];
            {
                uint4 h0 = *(const uint4*)(pBh + wb0);
                uint4 h1 = *(const uint4*)(pBh + wb1);
                uint4 h2 = *(const uint4*)(pBh + wb0 + 32);
                uint4 h3 = *(const uint4*)(pBh + wb1 + 32);
                uint4 l0 = *(const uint4*)(pBl + wb0);
                uint4 l1 = *(const uint4*)(pBl + wb1);
                uint4 l2 = *(const uint4*)(pBl + wb0 + 32);
                uint4 l3 = *(const uint4*)(pBl + wb1 + 32);
                bh[0][0] = h0.x; bh[1][0] = h0.y; bh[2][0] = h0.z; bh[3][0] = h0.w;
                bh[0][1] = h1.x; bh[1][1] = h1.y; bh[2][1] = h1.z; bh[3][1] = h1.w;
                bh[4][0] = h2.x; bh[5][0] = h2.y; bh[6][0] = h2.z; bh[7][0] = h2.w;
                bh[4][1] = h3.x; bh[5][1] = h3.y; bh[6][1] = h3.z; bh[7][1] = h3.w;
                bl[0][0] = l0.x; bl[1][0] = l0.y; bl[2][0] = l0.z; bl[3][0] = l0.w;
                bl[0][1] = l1.x; bl[1][1] = l1.y; bl[2][1] = l1.z; bl[3][1] = l1.w;
                bl[4][0] = l2.x; bl[5][0] = l2.y; bl[6][0] = l2.z; bl[7][0] = l2.w;
                bl[4][1] = l3.x; bl[5][1] = l3.y; bl[6][1] = l3.z; bl[7][1] = l3.w;
            }
            unsigned ah[2][4], al[2][4];
#pragma unroll
            for (int mf = 0; mf < 2; ++mf) {
                uint2 h0 = *(const uint2*)(pAh + wa0 + mf * 16);
                uint2 h1 = *(const uint2*)(pAh + wa1 + mf * 16);
                uint2 l0 = *(const uint2*)(pAl + wa0 + mf * 16);
                uint2 l1 = *(const uint2*)(pAl + wa1 + mf * 16);
                ah[mf][0] = h0.x; ah[mf][1] = h0.y; ah[mf][2] = h1.x; ah[mf][3] = h1.y;
                al[mf][0] = l0.x; al[mf][1] = l0.y; al[mf][2] = l1.x; al[mf][3] = l1.y;
            }
#pragma unroll
            for (int mf = 0; mf < 2; ++mf)
#pragma unroll
                for (int nf = 0; nf < 8; ++nf)
                    mma_tf32(acc[mf][nf], al[mf], bh[nf]);
#pragma unroll
            for (int mf = 0; mf < 2; ++mf)
#pragma unroll
                for (int nf = 0; nf < 8; ++nf)
                    mma_tf32(acc[mf][nf], ah[mf], bl[nf]);
#pragma unroll
            for (int mf = 0; mf < 2; ++mf)
#pragma unroll
                for (int nf = 0; nf < 8; ++nf)
                    mma_tf32(acc[mf][nf], ah[mf], bh[nf]);

            if (kt + 2 < ktiles) {
                int s = (cur + 2) % 3;
                ISSUE_(s, kt + 2);
            } else {
                asm volatile("cp.async.commit_group;" ::: "memory");
            }
            cur = (cur + 1) % 3;
        }
#undef ISSUE_

        const int cc2 = lc * 2;
#pragma unroll
        for (int mf = 0; mf < 2; ++mf) {
            const int r0 = by * 128 + wm + mf * 16 + rr;
#pragma unroll
            for (int nf = 0; nf < 8; ++nf) {
                const int col = bx * 64 + nf * 8 + cc2;
                float b0 = bias ? bias[col] : 0.f;
                float b1 = bias ? bias[col + 1] : 0.f;
                float v0 = acc[mf][nf][0] + b0, v1 = acc[mf][nf][1] + b1;
                float v2 = acc[mf][nf][2] + b0, v3 = acc[mf][nf][3] + b1;
                if (ACT == 1) {
                    v0 = fmaxf(v0, 0.f); v1 = fmaxf(v1, 0.f);
                    v2 = fmaxf(v2, 0.f); v3 = fmaxf(v3, 0.f);
                }
                float2 w0 = {v0, v1}, w1 = {v2, v3};
                *(float2*)(C + (size_t)r0 * N + col) = w0;
                *(float2*)(C + (size_t)(r0 + 8) * N + col) = w1;
            }
        }
    }
}

// ================= skinny GEMM with row-split B select ==========
template <int ACT, int NCOL, int NSL, int RPB>
__global__ void skinny_gemm(const float* __restrict__ A, const float* __restrict__ B,
                            const float* __restrict__ B2, const float* __restrict__ bias,
                            const float* __restrict__ bias2, float* __restrict__ C,
                            int N, int K, int rowsplit)
{
    __shared__ float sA[RPB][128];
    __shared__ float sred[NSL][RPB][NCOL];
    const int tid = threadIdx.x;
    const int row0 = blockIdx.x * RPB;
    if (row0 >= rowsplit) { B = B2; bias = bias2; }
    const int c = tid % NCOL, sl = tid / NCOL;
    const bool active = sl < NSL;
    const int kper = 128 / NSL;
    float acc[RPB];
#pragma unroll
    for (int r = 0; r < RPB; ++r) acc[r] = 0.f;

    for (int k0 = 0; k0 < K; k0 += 128) {
        __syncthreads();
        for (int i = tid; i < RPB * 128; i += 256) {
            int r = i >> 7, kk = i & 127;
            sA[r][kk] = A[(size_t)(row0 + r) * K + k0 + kk];
        }
        __syncthreads();
        if (active) {
            for (int kk = sl * kper; kk < (sl + 1) * kper; ++kk) {
                float b = B[(size_t)(k0 + kk) * N + c];
#pragma unroll
                for (int r = 0; r < RPB; ++r) acc[r] = fmaf(sA[r][kk], b, acc[r]);
            }
        }
    }
    if (active) {
#pragma unroll
        for (int r = 0; r < RPB; ++r) sred[sl][r][c] = acc[r];
    }
    __syncthreads();
    for (int i = tid; i < RPB * NCOL; i += 256) {
        int r = i / NCOL, cc = i % NCOL;
        float s = 0.f;
#pragma unroll
        for (int q = 0; q < NSL; ++q) s += sred[q][r][cc];
        if (bias) s += bias[cc];
        if (ACT == 2) s = 1.f / (1.f + expf(-s));
        C[(size_t)(row0 + r) * N + cc] = s;
    }
}

// ---------------- kb/vb construction ----------------
__global__ void build_kb_vb(const float* __restrict__ k_pos, const float* __restrict__ v_pos)
{
    int idx = blockIdx.x * blockDim.x + threadIdx.x;
    if (idx >= KVH_ * NC_ * CDIM_) return;
    int d = idx & 63;
    int i = (idx >> 6) & 15;
    int c = (idx >> 10) & 127;
    int h = idx >> 17;
    int t = c * 16 + i;
    float kv = g_qkv[(size_t)t * QKV_W + DIM_ + h * DH_ + d];
    float vv = g_qkv[(size_t)t * QKV_W + DIM_ + 512 + h * DH_ + d];
    g_kbv[idx]                      = kv + k_pos[(h * 16 + i) * 64 + d];
    g_kbv[idx + KVH_ * NC_ * CDIM_] = vv + v_pos[(h * 16 + i) * 64 + d];
}

// ---------------- assemble ck/cv ----------------
__global__ void assemble_c(const float* __restrict__ mem, float* __restrict__ dst,
                           const float* __restrict__ body)
{
    int idx = blockIdx.x * blockDim.x + threadIdx.x;
    if (idx >= KVH_ * 129 * DH_) return;
    int d = idx % 64;
    int j = (idx / 64) % 129;
    int h = idx / (64 * 129);
    dst[idx] = (j == 0) ? mem[h * 64 + d] : body[((h * NC_) + (j - 1)) * 64 + d];
}

// ---------------- compression attention (UNCHANGED: feeds topk, bitwise) ---
__global__ void csoft_kernel()
{
    __shared__ float sp[8][4][132];
    int gw = (blockIdx.x * blockDim.x + threadIdx.x) >> 5;
    int lane = threadIdx.x & 31, wl = (threadIdx.x >> 5) & 7;
    if (gw >= KVH_ * S_LEN) return;
    int h = gw >> 11, n = gw & (S_LEN - 1);
    const float* qb = g_qkv + (size_t)n * QKV_W + h * 4 * DH_;
    float q0[4], q1[4];
#pragma unroll
    for (int g = 0; g < 4; ++g) { q0[g] = qb[g * 64 + lane]; q1[g] = qb[g * 64 + lane + 32]; }
    const float* ckh = g_ck + h * 129 * 64;
    const int nvalid = (n >> 4) + 1;

    float m[4] = {-1e38f, -1e38f, -1e38f, -1e38f};
    for (int j = 0; j < nvalid; ++j) {
        const float* kr = ckh + j * 64;
        float k0 = kr[lane], k1 = kr[lane + 32];
#pragma unroll
        for (int g = 0; g < 4; ++g) {
            float s = q0[g] * k0 + q1[g] * k1;
#pragma unroll
            for (int o = 16; o; o >>= 1) s += __shfl_xor_sync(0xffffffffu, s, o);
            s *= SCALE_;
            if (lane == 0) sp[wl][g][j] = s;
            m[g] = fmaxf(m[g], s);
        }
    }
    __syncwarp();
#pragma unroll
    for (int g = 0; g < 4; ++g) {
        float* out = g_csim + (((size_t)(h * 4 + g) * S_LEN) + n) * 129;
        for (int j = lane; j < 129; j += 32) out[j] = (j < nvalid) ? sp[wl][g][j] : NEGV;
    }
    float sum[4] = {0.f, 0.f, 0.f, 0.f};
    for (int j = lane; j < nvalid; j += 32) {
#pragma unroll
        for (int g = 0; g < 4; ++g) {
            float e = expf(sp[wl][g][j] - m[g]);
            sp[wl][g][j] = e;
            sum[g] += e;
        }
    }
#pragma unroll
    for (int g = 0; g < 4; ++g)
#pragma unroll
        for (int o = 16; o; o >>= 1) sum[g] += __shfl_xor_sync(0xffffffffu, sum[g], o);
    __syncwarp();
    const float* cvh = g_cv + h * 129 * 64;
    float a0[4] = {0.f, 0.f, 0.f, 0.f}, a1[4] = {0.f, 0.f, 0.f, 0.f};
    for (int j = 0; j < nvalid; ++j) {
        float v0 = cvh[j * 64 + lane], v1 = cvh[j * 64 + lane + 32];
#pragma unroll
        for (int g = 0; g < 4; ++g) {
            float p = sp[wl][g][j];
            a0[g] = fmaf(p, v0, a0[g]);
            a1[g] = fmaf(p, v1, a1[g]);
        }
    }
#pragma unroll
    for (int g = 0; g < 4; ++g) {
        float inv = 1.f / sum[g];
        size_t o = (((size_t)(h * 4 + g) * S_LEN) + n) * 64;
        g_cout[o + lane]      = a0[g] * inv;
        g_cout[o + lane + 32] = a1[g] * inv;
    }
}

// ---------------- importance + top-8 selection ----------------
__global__ void topk_kernel()
{
    int w = (blockIdx.x * blockDim.x + threadIdx.x) >> 5;
    int lane = threadIdx.x & 31;
    if (w >= KVH_ * S_LEN) return;
    int h = w >> 11, n = w & (S_LEN - 1);
    float vals[4];
    int js[4];
#pragma unroll
    for (int r = 0; r < 4; ++r) {
        int jj = lane + r * 32;
        float s = 0.f;
        for (int g = 0; g < 4; ++g)
            s += g_csim[(((size_t)(h * 4 + g) * S_LEN + n) * 129) + jj + 1];
        vals[r] = s * 0.25f;
        js[r] = jj;
    }
    float m = -1000.f;
#pragma unroll
    for (int r = 0; r < 4; ++r) m = fmaxf(m, vals[r]);
#pragma unroll
    for (int o = 16; o; o >>= 1) m = fmaxf(m, __shfl_xor_sync(0xffffffffu, m, o));
    float sum = 0.f;
#pragma unroll
    for (int r = 0; r < 4; ++r) sum += expf(vals[r] - m);
#pragma unroll
    for (int o = 16; o; o >>= 1) sum += __shfl_xor_sync(0xffffffffu, sum, o);
    sum += expf(-1000.f - m);
    for (int t = 0; t < 8; ++t) {
        float bv = vals[0]; int bj = js[0];
#pragma unroll
        for (int r = 1; r < 4; ++r)
            if (vals[r] > bv || (vals[r] == bv && js[r] < bj)) { bv = vals[r]; bj = js[r]; }
        float v = bv; int j = bj;
#pragma unroll
        for (int o = 16; o; o >>= 1) {
            float vo = __shfl_xor_sync(0xffffffffu, v, o);
            int   jo = __shfl_xor_sync(0xffffffffu, j, o);
            if (vo > v || (vo == v && jo < j)) { v = vo; j = jo; }
        }
        if (lane == 0) {
            g_selidx[w * 8 + t] = j;
            float p = expf(v - m) / sum;
            g_selmask[w * 8 + t] = (p > 1e-10f) ? 1 : 0;
        }
        int owner = j & 31, rr = j >> 5;
        if (lane == owner) vals[rr] = -INFINITY;
    }
}

// ---------------- RoPE ----------------
__global__ void rope_table()
{
    int idx = blockIdx.x * blockDim.x + threadIdx.x;
    if (idx >= S_LEN * 32) return;
    int p = idx & 31;
    int n = idx >> 5;
    double inv = pow(10000.0, -((double)(2 * p)) / 64.0);
    double a = (double)n * inv;
    g_rcs[idx * 2]     = (float)cos(a);
    g_rcs[idx * 2 + 1] = (float)sin(a);
}

__global__ void rope_apply()
{
    int idx = blockIdx.x * blockDim.x + threadIdx.x;
    if (idx >= 40 * S_LEN * 32) return;
    int p = idx & 31;
    int n = (idx >> 5) & (S_LEN - 1);
    int hh = idx >> 16;
    float c = g_rcs[(n * 32 + p) * 2];
    float s = g_rcs[(n * 32 + p) * 2 + 1];
    const float* src; float* dst;
    if (hh < 32) {
        src = g_qkv + (size_t)n * QKV_W + hh * DH_;
        dst = g_rq + ((size_t)hh * S_LEN + n) * DH_;
    } else {
        int h = hh - 32;
        src = g_qkv + (size_t)n * QKV_W + DIM_ + h * DH_;
        dst = g_rk + ((size_t)h * S_LEN + n) * DH_;
    }
    float x1 = src[2 * p], x2 = src[2 * p + 1];
    dst[2 * p]     = x1 * c - x2 * s;
    dst[2 * p + 1] = x1 * s + x2 * c;
}

// ---------------- fine attention: 4g x 8lane partition (sim pass) ----------
__global__ void fine_kernel()
{
    __shared__ float sp[8][4][144];
    int gw = (blockIdx.x * blockDim.x + threadIdx.x) >> 5;
    int lane = threadIdx.x & 31, wl = (threadIdx.x >> 5) & 7;
    if (gw >= KVH_ * S_LEN) return;
    int h = gw >> 11, n = gw & (S_LEN - 1);
    const int g = lane >> 3, sl = lane & 7;
    // q slice for this lane's g-head: elements [sl*8, sl*8+8)
    const float* qp = g_rq + (((size_t)(h * 4 + g) * S_LEN) + n) * 64 + sl * 8;
    const float4 qa = *(const float4*)qp;
    const float4 qb = *(const float4*)(qp + 4);
    const int base = (h * S_LEN + n) * 8;
    const int ownb = n >> 4;

    float mloc = -1e38f;
    for (int j = 0; j < 144; ++j) {
        int bsel = j >> 4, off = j & 15;
        int blk; bool valid;
        if (bsel < 8) { blk = g_selidx[base + bsel]; valid = g_selmask[base + bsel] != 0; }
        else          { blk = ownb;                  valid = (n & 15) >= off; }
        float s = NEGV;
        if (valid) {
            const float* kr = g_rk + ((size_t)h * S_LEN + blk * 16 + off) * 64 + sl * 8;
            float4 ka = *(const float4*)kr;
            float4 kb = *(const float4*)(kr + 4);
            float t = qa.x * ka.x + qa.y * ka.y + qa.z * ka.z + qa.w * ka.w
                    + qb.x * kb.x + qb.y * kb.y + qb.z * kb.z + qb.w * kb.w;
            t += __shfl_xor_sync(0xffffffffu, t, 1);
            t += __shfl_xor_sync(0xffffffffu, t, 2);
            t += __shfl_xor_sync(0xffffffffu, t, 4);
            s = t * SCALE_;
        }
        if (sl == 0) sp[wl][g][j] = s;
        mloc = fmaxf(mloc, s);
    }
    __syncwarp();
    float mg[4];
#pragma unroll
    for (int gg = 0; gg < 4; ++gg) mg[gg] = __shfl_sync(0xffffffffu, mloc, gg * 8);
    float sum[4] = {0.f, 0.f, 0.f, 0.f};
    for (int j = lane; j < 144; j += 32) {
#pragma unroll
        for (int gg = 0; gg < 4; ++gg) {
            float e = expf(sp[wl][gg][j] - mg[gg]);
            sp[wl][gg][j] = e;
            sum[gg] += e;
        }
    }
#pragma unroll
    for (int gg = 0; gg < 4; ++gg)
#pragma unroll
        for (int o = 16; o; o >>= 1) sum[gg] += __shfl_xor_sync(0xffffffffu, sum[gg], o);
    __syncwarp();
    float a0[4] = {0.f, 0.f, 0.f, 0.f}, a1[4] = {0.f, 0.f, 0.f, 0.f};
    for (int j = 0; j < 144; ++j) {
        int bsel = j >> 4, off = j & 15;
        int blk = (bsel < 8) ? g_selidx[base + bsel] : ownb;
        int t = blk * 16 + off;
        const float* vr = g_qkv + (size_t)t * QKV_W + DIM_ + 512 + h * DH_;
        float v0 = vr[lane], v1 = vr[lane + 32];
#pragma unroll
        for (int gg = 0; gg < 4; ++gg) {
            float p = sp[wl][gg][j];
            a0[gg] = fmaf(p, v0, a0[gg]);
            a1[gg] = fmaf(p, v1, a1[gg]);
        }
    }
#pragma unroll
    for (int gg = 0; gg < 4; ++gg) {
        float inv = 1.f / sum[gg];
        size_t o = (((size_t)(h * 4 + gg) * S_LEN) + n) * 64;
        g_fout[o + lane]      = a0[gg] * inv;
        g_fout[o + lane + 32] = a1[gg] * inv;
    }
}

// ---------------- sliding-window attention: 4g x 8lane partition ----------
__global__ void slide_kernel()
{
    __shared__ float sp[8][4][66];
    int gw = (blockIdx.x * blockDim.x + threadIdx.x) >> 5;
    int lane = threadIdx.x & 31, wl = (threadIdx.x >> 5) & 7;
    if (gw >= KVH_ * S_LEN) return;
    int h = gw >> 11, n = gw & (S_LEN - 1);
    const int g = lane >> 3, sl = lane & 7;
    const float* qp = g_rq + (((size_t)(h * 4 + g) * S_LEN) + n) * 64 + sl * 8;
    const float4 qa = *(const float4*)qp;
    const float4 qb = *(const float4*)(qp + 4);
    int lo = n - 64; if (lo < 0) lo = 0;
    int cnt = n - lo + 1;

    float mloc = -1e38f;
    for (int jj = 0; jj < cnt; ++jj) {
        const float* kr = g_rk + ((size_t)h * S_LEN + lo + jj) * 64 + sl * 8;
        float4 ka = *(const float4*)kr;
        float4 kb = *(const float4*)(kr + 4);
        float t = qa.x * ka.x + qa.y * ka.y + qa.z * ka.z + qa.w * ka.w
                + qb.x * kb.x + qb.y * kb.y + qb.z * kb.z + qb.w * kb.w;
        t += __shfl_xor_sync(0xffffffffu, t, 1);
        t += __shfl_xor_sync(0xffffffffu, t, 2);
        t += __shfl_xor_sync(0xffffffffu, t, 4);
        float s = t * SCALE_;
        if (sl == 0) sp[wl][g][jj] = s;
        mloc = fmaxf(mloc, s);
    }
    __syncwarp();
    float mg[4];
#pragma unroll
    for (int gg = 0; gg < 4; ++gg) mg[gg] = __shfl_sync(0xffffffffu, mloc, gg * 8);
    float sum[4] = {0.f, 0.f, 0.f, 0.f};
    for (int jj = lane; jj < cnt; jj += 32) {
#pragma unroll
        for (int gg = 0; gg < 4; ++gg) {
            float e = expf(sp[wl][gg][jj] - mg[gg]);
            sp[wl][gg][jj] = e;
            sum[gg] += e;
        }
    }
#pragma unroll
    for (int gg = 0; gg < 4; ++gg)
#pragma unroll
        for (int o = 16; o; o >>= 1) sum[gg] += __shfl_xor_sync(0xffffffffu, sum[gg], o);
    __syncwarp();
    float a0[4] = {0.f, 0.f, 0.f, 0.f}, a1[4] = {0.f, 0.f, 0.f, 0.f};
    for (int jj = 0; jj < cnt; ++jj) {
        const float* vr = g_qkv + (size_t)(lo + jj) * QKV_W + DIM_ + 512 + h * DH_;
        float v0 = vr[lane], v1 = vr[lane + 32];
#pragma unroll
        for (int gg = 0; gg < 4; ++gg) {
            float p = sp[wl][gg][jj];
            a0[gg] = fmaf(p, v0, a0[gg]);
            a1[gg] = fmaf(p, v1, a1[gg]);
        }
    }
#pragma unroll
    for (int gg = 0; gg < 4; ++gg) {
        float inv = 1.f / sum[gg];
        size_t o = (((size_t)(h * 4 + gg) * S_LEN) + n) * 64;
        g_sout[o + lane]      = a0[gg] * inv;
        g_sout[o + lane + 32] = a1[gg] * inv;
    }
}

// ---------------- launcher ----------------
extern "C" void kernel_launch(void* const* d_in, const int* in_sizes, int n_in,
                              void* d_out, int out_size)
{
    const float* x      = (const float*)d_in[0];
    const float* w_qkv  = (const float*)d_in[1];
    const float* k_pos  = (const float*)d_in[2];
    const float* v_pos  = (const float*)d_in[3];
    const float* k_cw1  = (const float*)d_in[4];
    const float* k_cb1  = (const float*)d_in[5];
    const float* k_cw2  = (const float*)d_in[6];
    const float* k_cb2  = (const float*)d_in[7];
    const float* v_cw1  = (const float*)d_in[8];
    const float* v_cb1  = (const float*)d_in[9];
    const float* v_cw2  = (const float*)d_in[10];
    const float* v_cb2  = (const float*)d_in[11];
    const float* mem_ck = (const float*)d_in[12];
    const float* mem_cv = (const float*)d_in[13];
    const float* w_gate = (const float*)d_in[14];
    const float* b_gate = (const float*)d_in[15];
    const float* w_out  = (const float*)d_in[16];
    float* out = (float*)d_out;

    float *qkv, *kbv, *h1, *body, *gate, *ck, *cv;
    cudaGetSymbolAddress((void**)&qkv,  g_qkv);
    cudaGetSymbolAddress((void**)&kbv,  g_kbv);
    cudaGetSymbolAddress((void**)&h1,   g_h1);
    cudaGetSymbolAddress((void**)&body, g_body);
    cudaGetSymbolAddress((void**)&gate, g_gate);
    cudaGetSymbolAddress((void**)&ck,   g_ck);
    cudaGetSymbolAddress((void**)&cv,   g_cv);

    const int NOSPLIT = 1 << 30;

    rope_table<<<(S_LEN * 32) / 256, 256>>>();
    // 1) qkv projection
    split_At<<<dim3(DIM_ / 32, S_LEN / 32), 256>>>(x, S_LEN, DIM_);
    split_B<<<(DIM_ * QKV_W) / 256, 256>>>(w_qkv, 0, QKV_W, DIM_ * QKV_W);
    gemm3p<0><<<PGRID, 128>>>(nullptr, nullptr, qkv, S_LEN, QKV_W, DIM_,
                              768, QKV_W / 64, NOSPLIT, 0);
    // 2) compression inputs
    build_kb_vb<<<(KVH_ * NC_ * CDIM_) / 256, 256>>>(k_pos, v_pos);
    // 3) merged K+V compression MLP layer 1
    split_At<<<dim3(CDIM_ / 32, 2048 / 32), 256>>>(kbv, 2048, CDIM_);
    split_B<<<(CDIM_ * CDIM_) / 256, 256>>>(k_cw1, 0, CDIM_, CDIM_ * CDIM_);
    split_B<<<(CDIM_ * CDIM_) / 256, 256>>>(v_cw1, (size_t)CDIM_ * CDIM_, CDIM_, CDIM_ * CDIM_);
    gemm3p<1><<<256, 128>>>(k_cb1, v_cb1, h1, 2048, CDIM_, CDIM_,
                            256, 16, 8, (size_t)CDIM_ * CDIM_);
    skinny_gemm<0, 64, 4, 4><<<512, 256>>>(h1, k_cw2, v_cw2, k_cb2, v_cb2, body,
                                           64, CDIM_, 1024);
    assemble_c<<<(KVH_ * 129 * DH_ + 255) / 256, 256>>>(mem_ck, ck, body);
    assemble_c<<<(KVH_ * 129 * DH_ + 255) / 256, 256>>>(mem_cv, cv, body + 1024 * 64);
    // 5) compression attention + top-k
    csoft_kernel<<<KVH_ * S_LEN / 8, 256>>>();
    topk_kernel<<<KVH_ * S_LEN / 8, 256>>>();
    // 6) RoPE apply
    rope_apply<<<(40 * S_LEN * 32) / 256, 256>>>();
    // 7) fine + sliding attention (restructured sim pass)
    fine_kernel<<<KVH_ * S_LEN / 8, 256>>>();
    slide_kernel<<<KVH_ * S_LEN / 8, 256>>>();
    // 8) gates
    skinny_gemm<2, 96, 2, 4><<<512, 256>>>(x, w_gate, w_gate, b_gate, b_gate, gate,
                                           96, DIM_, NOSPLIT);
    // 9) fused combine+split, then output projection
    combine_split<<<dim3(DIM_ / 32, S_LEN / 32), 256>>>();
    split_B<<<(DIM_ * DIM_) / 256, 256>>>(w_out, 0, DIM_, DIM_ * DIM_);
    gemm3p<0><<<PGRID, 128>>>(nullptr, nullptr, out, S_LEN, DIM_, DIM_,
                              512, DIM_ / 64, NOSPLIT, 0);
}

// round 16
// speedup vs baseline: 1.1149x; 1.0477x over previous
#include <cuda_runtime.h>
#include <math.h>

// ---------------- problem constants ----------------
#define S_LEN 2048
#define QKV_W 3072
#define DIM_  2048
#define DH_   64
#define KVH_  8
#define HEADS_ 32
#define CDIM_ 1024
#define NC_   128
#define NEGV  (-1e30f)
#define SCALE_ 0.125f
#define PGRID 444

// ---------------- scratch ----------------
__device__ float g_qkv [S_LEN * QKV_W];
__device__ float g_kbv [2 * KVH_ * NC_ * CDIM_];
__device__ float g_h1  [2 * KVH_ * NC_ * CDIM_];
__device__ float g_body[2 * KVH_ * NC_ * DH_];
__device__ float g_ck  [KVH_ * 129 * DH_];
__device__ float g_cv  [KVH_ * 129 * DH_];
__device__ float g_csim[HEADS_ * S_LEN * 129];
__device__ float g_cout[HEADS_ * S_LEN * DH_];
__device__ float g_fout[HEADS_ * S_LEN * DH_];
__device__ float g_sout[HEADS_ * S_LEN * DH_];
__device__ float g_rq  [HEADS_ * S_LEN * DH_];
__device__ float g_rk  [KVH_  * S_LEN * DH_];
__device__ float g_rcs [S_LEN * 32 * 2];
__device__ int           g_selidx [KVH_ * S_LEN * 8];
__device__ unsigned char g_selmask[KVH_ * S_LEN * 8];
__device__ float g_gate[S_LEN * 96];
// split operand scratch (fragment-interleaved layouts)
__device__ unsigned g_Ahi[DIM_ * S_LEN];
__device__ unsigned g_Alo[DIM_ * S_LEN];
__device__ unsigned g_Bhi[DIM_ * QKV_W];
__device__ unsigned g_Blo[DIM_ * QKV_W];

__device__ __forceinline__ int pB_(int n) { return (n & ~31) + ((n & 7) << 2) + ((n >> 3) & 3); }

// ================= split helpers =================
__device__ __forceinline__ unsigned f2tf(float x)
{
    unsigned r;
    asm("cvt.rna.tf32.f32 %0, %1;" : "=r"(r) : "f"(x));
    return r;
}

__device__ __forceinline__ void split_tf(float x, unsigned& hi, unsigned& lo)
{
    hi = f2tf(x);
    lo = f2tf(x - __uint_as_float(hi));
}

__device__ __forceinline__ void mma_tf32(float* c, const unsigned* a, const unsigned* b)
{
    asm volatile(
        "mma.sync.aligned.m16n8k8.row.col.f32.tf32.tf32.f32 "
        "{%0,%1,%2,%3}, {%4,%5,%6,%7}, {%8,%9}, {%0,%1,%2,%3};"
        : "+f"(c[0]), "+f"(c[1]), "+f"(c[2]), "+f"(c[3])
        : "r"(a[0]), "r"(a[1]), "r"(a[2]), "r"(a[3]), "r"(b[0]), "r"(b[1]));
}

__device__ __forceinline__ void cp16(unsigned saddr, const void* g)
{
    asm volatile("cp.async.ca.shared.global [%0], [%1], 16;" :: "r"(saddr), "l"(g));
}

// split + transpose A
__global__ void split_At(const float* __restrict__ A, int M, int K)
{
    __shared__ float t[32][33];
    const int tid = threadIdx.x;
    const int k0 = blockIdx.x * 32, m0 = blockIdx.y * 32;
    const int c = tid & 31, r = tid >> 5;
#pragma unroll
    for (int i = r; i < 32; i += 8)
        t[i][c] = A[(size_t)(m0 + i) * K + k0 + c];
    __syncthreads();
#pragma unroll
    for (int i = r; i < 32; i += 8) {
        unsigned hi, lo;
        split_tf(t[c][i], hi, lo);
        size_t o = (size_t)(k0 + i) * M + m0 + ((c & 16) + ((c & 7) << 1) + ((c >> 3) & 1));
        g_Ahi[o] = hi;
        g_Alo[o] = lo;
    }
}

// split B
__global__ void split_B(const float* __restrict__ B, size_t off, int N, int total)
{
    int idx = blockIdx.x * blockDim.x + threadIdx.x;
    if (idx >= total) return;
    int n = idx % N, k = idx / N;
    unsigned hi, lo;
    split_tf(B[idx], hi, lo);
    size_t o = off + (size_t)k * N + pB_(n);
    g_Bhi[o] = hi;
    g_Blo[o] = lo;
}

// fused gated-combine + split + transpose
__global__ void combine_split(void)
{
    __shared__ float t[32][33];
    const int tid = threadIdx.x;
    const int c0 = blockIdx.x * 32;
    const int n0 = blockIdx.y * 32;
    const int c = tid & 31, r = tid >> 5;
    const int hg = c0 >> 6;
#pragma unroll
    for (int i = r; i < 32; i += 8) {
        int n = n0 + i;
        float gg0 = g_gate[n * 96 + hg * 3];
        float gg1 = g_gate[n * 96 + hg * 3 + 1];
        float gg2 = g_gate[n * 96 + hg * 3 + 2];
        size_t src = ((size_t)hg * S_LEN + n) * 64 + ((c0 + c) & 63);
        t[i][c] = gg0 * g_cout[src] + gg1 * g_fout[src] + gg2 * g_sout[src];
    }
    __syncthreads();
#pragma unroll
    for (int i = r; i < 32; i += 8) {
        unsigned hi, lo;
        split_tf(t[c][i], hi, lo);
        size_t o = (size_t)(c0 + i) * DIM_ + n0 + ((c & 16) + ((c & 7) << 1) + ((c >> 3) & 1));
        g_Ahi[o] = hi;
        g_Alo[o] = lo;
    }
}

// ================= 3-product TF32 GEMM, persistent grid-strided ============
template <int ACT>
__global__ void __launch_bounds__(128, 3)
gemm3p(const float* __restrict__ bias0, const float* __restrict__ bias1,
       float* __restrict__ C, int M, int N, int K,
       int ntiles, int bxdim, int bysplit, size_t boff)
{
    __shared__ __align__(16) unsigned Ah[3][8][136], Al[3][8][136];
    __shared__ __align__(16) unsigned Bh[3][8][72],  Bl[3][8][72];
    const int tid = threadIdx.x;
    const int lane = tid & 31;
    const int wid = tid >> 5;
    const int wm = wid * 32;

    const int ar0 = tid >> 5;
    const int ac0 = (tid & 31) << 2;
    const int ar1 = (tid + 128) >> 5;
    const int brow = tid >> 4;
    const int bc4  = (tid & 15) << 2;

    const unsigned sAh = (unsigned)__cvta_generic_to_shared(&Ah[0][0][0]);
    const unsigned sAl = (unsigned)__cvta_generic_to_shared(&Al[0][0][0]);
    const unsigned sBh = (unsigned)__cvta_generic_to_shared(&Bh[0][0][0]);
    const unsigned sBl = (unsigned)__cvta_generic_to_shared(&Bl[0][0][0]);
    const unsigned aoff0 = (unsigned)(ar0 * 136 + ac0) * 4u;
    const unsigned aoff1 = (unsigned)(ar1 * 136 + ac0) * 4u;
    const unsigned boffs = (unsigned)(brow * 72 + bc4) * 4u;

    const int rr = lane >> 2;
    const int lc = lane & 3;
    const int k0 = lc, k1 = lc + 4;
    const int ktiles = K >> 3;

    for (int tile = blockIdx.x; tile < ntiles; tile += gridDim.x) {
        const int bx = tile % bxdim;
        const int by = tile / bxdim;
        const bool second = (by >= bysplit);
        const size_t bofs = second ? boff : 0;
        const float* bias = second ? bias1 : bias0;
        const size_t abase = (size_t)by * 128;
        const size_t bbase = (size_t)bx * 64;

        __syncthreads();

#define ISSUE_(s, kt) do {                                                   \
        size_t a0_ = (size_t)((kt) * 8 + ar0) * M + abase + ac0;             \
        size_t a1_ = (size_t)((kt) * 8 + ar1) * M + abase + ac0;             \
        cp16(sAh + (unsigned)(s) * 4352u + aoff0, g_Ahi + a0_);              \
        cp16(sAh + (unsigned)(s) * 4352u + aoff1, g_Ahi + a1_);              \
        cp16(sAl + (unsigned)(s) * 4352u + aoff0, g_Alo + a0_);              \
        cp16(sAl + (unsigned)(s) * 4352u + aoff1, g_Alo + a1_);              \
        size_t bo_ = bofs + (size_t)((kt) * 8 + brow) * N + bbase + bc4;     \
        cp16(sBh + (unsigned)(s) * 2304u + boffs, g_Bhi + bo_);              \
        cp16(sBl + (unsigned)(s) * 2304u + boffs, g_Blo + bo_);              \
        asm volatile("cp.async.commit_group;" ::: "memory");                 \
    } while (0)

        ISSUE_(0, 0);
        ISSUE_(1, 1);

        float acc[2][8][4];
#pragma unroll
        for (int mf = 0; mf < 2; ++mf)
#pragma unroll
            for (int nf = 0; nf < 8; ++nf)
#pragma unroll
                for (int i = 0; i < 4; ++i) acc[mf][nf][i] = 0.f;

        int cur = 0;
        for (int kt = 0; kt < ktiles; ++kt) {
            asm volatile("cp.async.wait_group 1;" ::: "memory");
            __syncthreads();

            const unsigned* pAh = &Ah[cur][0][0];
            const unsigned* pAl = &Al[cur][0][0];
            const unsigned* pBh = &Bh[cur][0][0];
            const unsigned* pBl = &Bl[cur][0][0];
            const int wa0 = k0 * 136 + wm + 2 * rr;
            const int wa1 = k1 * 136 + wm + 2 * rr;
            const int wb0 = k0 * 72 + 4 * rr;
            const int wb1 = k1 * 72 + 4 * rr;

            unsigned bh[8][2], bl[8][2];
            {
                uint4 h0 = *(const uint4*)(pBh + wb0);
                uint4 h1 = *(const uint4*)(pBh + wb1);
                uint4 h2 = *(const uint4*)(pBh + wb0 + 32);
                uint4 h3 = *(const uint4*)(pBh + wb1 + 32);
                uint4 l0 = *(const uint4*)(pBl + wb0);
                uint4 l1 = *(const uint4*)(pBl + wb1);
                uint4 l2 = *(const uint4*)(pBl + wb0 + 32);
                uint4 l3 = *(const uint4*)(pBl + wb1 + 32);
                bh[0][0] = h0.x; bh[1][0] = h0.y; bh[2][0] = h0.z; bh[3][0] = h0.w;
                bh[0][1] = h1.x; bh[1][1] = h1.y; bh[2][1] = h1.z; bh[3][1] = h1.w;
                bh[4][0] = h2.x; bh[5][0] = h2.y; bh[6][0] = h2.z; bh[7][0] = h2.w;
                bh[4][1] = h3.x; bh[5][1] = h3.y; bh[6][1] = h3.z; bh[7][1] = h3.w;
                bl[0][0] = l0.x; bl[1][0] = l0.y; bl[2][0] = l0.z; bl[3][0] = l0.w;
                bl[0][1] = l1.x; bl[1][1] = l1.y; bl[2][1] = l1.z; bl[3][1] = l1.w;
                bl[4][0] = l2.x; bl[5][0] = l2.y; bl[6][0] = l2.z; bl[7][0] = l2.w;
                bl[4][1] = l3.x; bl[5][1] = l3.y; bl[6][1] = l3.z; bl[7][1] = l3.w;
            }
            unsigned ah[2][4], al[2][4];
#pragma unroll
            for (int mf = 0; mf < 2; ++mf) {
                uint2 h0 = *(const uint2*)(pAh + wa0 + mf * 16);
                uint2 h1 = *(const uint2*)(pAh + wa1 + mf * 16);
                uint2 l0 = *(const uint2*)(pAl + wa0 + mf * 16);
                uint2 l1 = *(const uint2*)(pAl + wa1 + mf * 16);
                ah[mf][0] = h0.x; ah[mf][1] = h0.y; ah[mf][2] = h1.x; ah[mf][3] = h1.y;
                al[mf][0] = l0.x; al[mf][1] = l0.y; al[mf][2] = l1.x; al[mf][3] = l1.y;
            }
#pragma unroll
            for (int mf = 0; mf < 2; ++mf)
#pragma unroll
                for (int nf = 0; nf < 8; ++nf)
                    mma_tf32(acc[mf][nf], al[mf], bh[nf]);
#pragma unroll
            for (int mf = 0; mf < 2; ++mf)
#pragma unroll
                for (int nf = 0; nf < 8; ++nf)
                    mma_tf32(acc[mf][nf], ah[mf], bl[nf]);
#pragma unroll
            for (int mf = 0; mf < 2; ++mf)
#pragma unroll
                for (int nf = 0; nf < 8; ++nf)
                    mma_tf32(acc[mf][nf], ah[mf], bh[nf]);

            if (kt + 2 < ktiles) {
                int s = (cur + 2) % 3;
                ISSUE_(s, kt + 2);
            } else {
                asm volatile("cp.async.commit_group;" ::: "memory");
            }
            cur = (cur + 1) % 3;
        }
#undef ISSUE_

        const int cc2 = lc * 2;
#pragma unroll
        for (int mf = 0; mf < 2; ++mf) {
            const int r0 = by * 128 + wm + mf * 16 + rr;
#pragma unroll
            for (int nf = 0; nf < 8; ++nf) {
                const int col = bx * 64 + nf * 8 + cc2;
                float b0 = bias ? bias[col] : 0.f;
                float b1 = bias ? bias[col + 1] : 0.f;
                float v0 = acc[mf][nf][0] + b0, v1 = acc[mf][nf][1] + b1;
                float v2 = acc[mf][nf][2] + b0, v3 = acc[mf][nf][3] + b1;
                if (ACT == 1) {
                    v0 = fmaxf(v0, 0.f); v1 = fmaxf(v1, 0.f);
                    v2 = fmaxf(v2, 0.f); v3 = fmaxf(v3, 0.f);
                }
                float2 w0 = {v0, v1}, w1 = {v2, v3};
                *(float2*)(C + (size_t)r0 * N + col) = w0;
                *(float2*)(C + (size_t)(r0 + 8) * N + col) = w1;
            }
        }
    }
}

// ================= skinny GEMM with row-split B select ==========
template <int ACT, int NCOL, int NSL, int RPB>
__global__ void skinny_gemm(const float* __restrict__ A, const float* __restrict__ B,
                            const float* __restrict__ B2, const float* __restrict__ bias,
                            const float* __restrict__ bias2, float* __restrict__ C,
                            int N, int K, int rowsplit)
{
    __shared__ float sA[RPB][128];
    __shared__ float sred[NSL][RPB][NCOL];
    const int tid = threadIdx.x;
    const int row0 = blockIdx.x * RPB;
    if (row0 >= rowsplit) { B = B2; bias = bias2; }
    const int c = tid % NCOL, sl = tid / NCOL;
    const bool active = sl < NSL;
    const int kper = 128 / NSL;
    float acc[RPB];
#pragma unroll
    for (int r = 0; r < RPB; ++r) acc[r] = 0.f;

    for (int k0 = 0; k0 < K; k0 += 128) {
        __syncthreads();
        for (int i = tid; i < RPB * 128; i += 256) {
            int r = i >> 7, kk = i & 127;
            sA[r][kk] = A[(size_t)(row0 + r) * K + k0 + kk];
        }
        __syncthreads();
        if (active) {
            for (int kk = sl * kper; kk < (sl + 1) * kper; ++kk) {
                float b = B[(size_t)(k0 + kk) * N + c];
#pragma unroll
                for (int r = 0; r < RPB; ++r) acc[r] = fmaf(sA[r][kk], b, acc[r]);
            }
        }
    }
    if (active) {
#pragma unroll
        for (int r = 0; r < RPB; ++r) sred[sl][r][c] = acc[r];
    }
    __syncthreads();
    for (int i = tid; i < RPB * NCOL; i += 256) {
        int r = i / NCOL, cc = i % NCOL;
        float s = 0.f;
#pragma unroll
        for (int q = 0; q < NSL; ++q) s += sred[q][r][cc];
        if (bias) s += bias[cc];
        if (ACT == 2) s = 1.f / (1.f + expf(-s));
        C[(size_t)(row0 + r) * N + cc] = s;
    }
}

// ---------------- kb/vb construction ----------------
__global__ void build_kb_vb(const float* __restrict__ k_pos, const float* __restrict__ v_pos)
{
    int idx = blockIdx.x * blockDim.x + threadIdx.x;
    if (idx >= KVH_ * NC_ * CDIM_) return;
    int d = idx & 63;
    int i = (idx >> 6) & 15;
    int c = (idx >> 10) & 127;
    int h = idx >> 17;
    int t = c * 16 + i;
    float kv = g_qkv[(size_t)t * QKV_W + DIM_ + h * DH_ + d];
    float vv = g_qkv[(size_t)t * QKV_W + DIM_ + 512 + h * DH_ + d];
    g_kbv[idx]                      = kv + k_pos[(h * 16 + i) * 64 + d];
    g_kbv[idx + KVH_ * NC_ * CDIM_] = vv + v_pos[(h * 16 + i) * 64 + d];
}

// ---------------- assemble ck/cv ----------------
__global__ void assemble_c(const float* __restrict__ mem, float* __restrict__ dst,
                           const float* __restrict__ body)
{
    int idx = blockIdx.x * blockDim.x + threadIdx.x;
    if (idx >= KVH_ * 129 * DH_) return;
    int d = idx % 64;
    int j = (idx / 64) % 129;
    int h = idx / (64 * 129);
    dst[idx] = (j == 0) ? mem[h * 64 + d] : body[((h * NC_) + (j - 1)) * 64 + d];
}

// ---------------- compression attention: 4g x 8lane dot partition ----------
__global__ void csoft_kernel()
{
    __shared__ float sp[8][4][132];
    int gw = (blockIdx.x * blockDim.x + threadIdx.x) >> 5;
    int lane = threadIdx.x & 31, wl = (threadIdx.x >> 5) & 7;
    if (gw >= KVH_ * S_LEN) return;
    int h = gw >> 11, n = gw & (S_LEN - 1);
    const int g = lane >> 3, sl = lane & 7;
    const float* qp = g_qkv + (size_t)n * QKV_W + h * 4 * DH_ + g * 64 + sl * 8;
    const float4 qa = *(const float4*)qp;
    const float4 qb = *(const float4*)(qp + 4);
    const float* ckh = g_ck + h * 129 * 64;
    const int nvalid = (n >> 4) + 1;

    float mloc = -1e38f;
    for (int j = 0; j < nvalid; ++j) {
        const float* kr = ckh + j * 64 + sl * 8;
        float4 ka = *(const float4*)kr;
        float4 kb = *(const float4*)(kr + 4);
        float t = qa.x * ka.x + qa.y * ka.y + qa.z * ka.z + qa.w * ka.w
                + qb.x * kb.x + qb.y * kb.y + qb.z * kb.z + qb.w * kb.w;
        t += __shfl_xor_sync(0xffffffffu, t, 1);
        t += __shfl_xor_sync(0xffffffffu, t, 2);
        t += __shfl_xor_sync(0xffffffffu, t, 4);
        float s = t * SCALE_;
        if (sl == 0) sp[wl][g][j] = s;
        mloc = fmaxf(mloc, s);
    }
    __syncwarp();
    float mg[4];
#pragma unroll
    for (int gg = 0; gg < 4; ++gg) mg[gg] = __shfl_sync(0xffffffffu, mloc, gg * 8);
#pragma unroll
    for (int gg = 0; gg < 4; ++gg) {
        float* out = g_csim + (((size_t)(h * 4 + gg) * S_LEN) + n) * 129;
        for (int j = lane; j < 129; j += 32) out[j] = (j < nvalid) ? sp[wl][gg][j] : NEGV;
    }
    float sum[4] = {0.f, 0.f, 0.f, 0.f};
    for (int j = lane; j < nvalid; j += 32) {
#pragma unroll
        for (int gg = 0; gg < 4; ++gg) {
            float e = expf(sp[wl][gg][j] - mg[gg]);
            sp[wl][gg][j] = e;
            sum[gg] += e;
        }
    }
#pragma unroll
    for (int gg = 0; gg < 4; ++gg)
#pragma unroll
        for (int o = 16; o; o >>= 1) sum[gg] += __shfl_xor_sync(0xffffffffu, sum[gg], o);
    __syncwarp();
    const float* cvh = g_cv + h * 129 * 64;
    float a0[4] = {0.f, 0.f, 0.f, 0.f}, a1[4] = {0.f, 0.f, 0.f, 0.f};
    for (int j = 0; j < nvalid; ++j) {
        float v0 = cvh[j * 64 + lane], v1 = cvh[j * 64 + lane + 32];
#pragma unroll
        for (int gg = 0; gg < 4; ++gg) {
            float p = sp[wl][gg][j];
            a0[gg] = fmaf(p, v0, a0[gg]);
            a1[gg] = fmaf(p, v1, a1[gg]);
        }
    }
#pragma unroll
    for (int gg = 0; gg < 4; ++gg) {
        float inv = 1.f / sum[gg];
        size_t o = (((size_t)(h * 4 + gg) * S_LEN) + n) * 64;
        g_cout[o + lane]      = a0[gg] * inv;
        g_cout[o + lane + 32] = a1[gg] * inv;
    }
}

// ---------------- importance + top-8 selection ----------------
__global__ void topk_kernel()
{
    int w = (blockIdx.x * blockDim.x + threadIdx.x) >> 5;
    int lane = threadIdx.x & 31;
    if (w >= KVH_ * S_LEN) return;
    int h = w >> 11, n = w & (S_LEN - 1);
    float vals[4];
    int js[4];
#pragma unroll
    for (int r = 0; r < 4; ++r) {
        int jj = lane + r * 32;
        float s = 0.f;
        for (int g = 0; g < 4; ++g)
            s += g_csim[(((size_t)(h * 4 + g) * S_LEN + n) * 129) + jj + 1];
        vals[r] = s * 0.25f;
        js[r] = jj;
    }
    float m = -1000.f;
#pragma unroll
    for (int r = 0; r < 4; ++r) m = fmaxf(m, vals[r]);
#pragma unroll
    for (int o = 16; o; o >>= 1) m = fmaxf(m, __shfl_xor_sync(0xffffffffu, m, o));
    float sum = 0.f;
#pragma unroll
    for (int r = 0; r < 4; ++r) sum += expf(vals[r] - m);
#pragma unroll
    for (int o = 16; o; o >>= 1) sum += __shfl_xor_sync(0xffffffffu, sum, o);
    sum += expf(-1000.f - m);
    for (int t = 0; t < 8; ++t) {
        float bv = vals[0]; int bj = js[0];
#pragma unroll
        for (int r = 1; r < 4; ++r)
            if (vals[r] > bv || (vals[r] == bv && js[r] < bj)) { bv = vals[r]; bj = js[r]; }
        float v = bv; int j = bj;
#pragma unroll
        for (int o = 16; o; o >>= 1) {
            float vo = __shfl_xor_sync(0xffffffffu, v, o);
            int   jo = __shfl_xor_sync(0xffffffffu, j, o);
            if (vo > v || (vo == v && jo < j)) { v = vo; j = jo; }
        }
        if (lane == 0) {
            g_selidx[w * 8 + t] = j;
            float p = expf(v - m) / sum;
            g_selmask[w * 8 + t] = (p > 1e-10f) ? 1 : 0;
        }
        int owner = j & 31, rr = j >> 5;
        if (lane == owner) vals[rr] = -INFINITY;
    }
}

// ---------------- RoPE ----------------
__global__ void rope_table()
{
    int idx = blockIdx.x * blockDim.x + threadIdx.x;
    if (idx >= S_LEN * 32) return;
    int p = idx & 31;
    int n = idx >> 5;
    double inv = pow(10000.0, -((double)(2 * p)) / 64.0);
    double a = (double)n * inv;
    g_rcs[idx * 2]     = (float)cos(a);
    g_rcs[idx * 2 + 1] = (float)sin(a);
}

__global__ void rope_apply()
{
    int idx = blockIdx.x * blockDim.x + threadIdx.x;
    if (idx >= 40 * S_LEN * 32) return;
    int p = idx & 31;
    int n = (idx >> 5) & (S_LEN - 1);
    int hh = idx >> 16;
    float c = g_rcs[(n * 32 + p) * 2];
    float s = g_rcs[(n * 32 + p) * 2 + 1];
    const float* src; float* dst;
    if (hh < 32) {
        src = g_qkv + (size_t)n * QKV_W + hh * DH_;
        dst = g_rq + ((size_t)hh * S_LEN + n) * DH_;
    } else {
        int h = hh - 32;
        src = g_qkv + (size_t)n * QKV_W + DIM_ + h * DH_;
        dst = g_rk + ((size_t)h * S_LEN + n) * DH_;
    }
    float x1 = src[2 * p], x2 = src[2 * p + 1];
    dst[2 * p]     = x1 * c - x2 * s;
    dst[2 * p + 1] = x1 * s + x2 * c;
}

// ---------------- fine attention: 4g x 8lane partition (sim pass) ----------
__global__ void fine_kernel()
{
    __shared__ float sp[8][4][144];
    int gw = (blockIdx.x * blockDim.x + threadIdx.x) >> 5;
    int lane = threadIdx.x & 31, wl = (threadIdx.x >> 5) & 7;
    if (gw >= KVH_ * S_LEN) return;
    int h = gw >> 11, n = gw & (S_LEN - 1);
    const int g = lane >> 3, sl = lane & 7;
    const float* qp = g_rq + (((size_t)(h * 4 + g) * S_LEN) + n) * 64 + sl * 8;
    const float4 qa = *(const float4*)qp;
    const float4 qb = *(const float4*)(qp + 4);
    const int base = (h * S_LEN + n) * 8;
    const int ownb = n >> 4;

    float mloc = -1e38f;
    for (int j = 0; j < 144; ++j) {
        int bsel = j >> 4, off = j & 15;
        int blk; bool valid;
        if (bsel < 8) { blk = g_selidx[base + bsel]; valid = g_selmask[base + bsel] != 0; }
        else          { blk = ownb;                  valid = (n & 15) >= off; }
        float s = NEGV;
        if (valid) {
            const float* kr = g_rk + ((size_t)h * S_LEN + blk * 16 + off) * 64 + sl * 8;
            float4 ka = *(const float4*)kr;
            float4 kb = *(const float4*)(kr + 4);
            float t = qa.x * ka.x + qa.y * ka.y + qa.z * ka.z + qa.w * ka.w
                    + qb.x * kb.x + qb.y * kb.y + qb.z * kb.z + qb.w * kb.w;
            t += __shfl_xor_sync(0xffffffffu, t, 1);
            t += __shfl_xor_sync(0xffffffffu, t, 2);
            t += __shfl_xor_sync(0xffffffffu, t, 4);
            s = t * SCALE_;
        }
        if (sl == 0) sp[wl][g][j] = s;
        mloc = fmaxf(mloc, s);
    }
    __syncwarp();
    float mg[4];
#pragma unroll
    for (int gg = 0; gg < 4; ++gg) mg[gg] = __shfl_sync(0xffffffffu, mloc, gg * 8);
    float sum[4] = {0.f, 0.f, 0.f, 0.f};
    for (int j = lane; j < 144; j += 32) {
#pragma unroll
        for (int gg = 0; gg < 4; ++gg) {
            float e = expf(sp[wl][gg][j] - mg[gg]);
            sp[wl][gg][j] = e;
            sum[gg] += e;
        }
    }
#pragma unroll
    for (int gg = 0; gg < 4; ++gg)
#pragma unroll
        for (int o = 16; o; o >>= 1) sum[gg] += __shfl_xor_sync(0xffffffffu, sum[gg], o);
    __syncwarp();
    float a0[4] = {0.f, 0.f, 0.f, 0.f}, a1[4] = {0.f, 0.f, 0.f, 0.f};
    for (int j = 0; j < 144; ++j) {
        int bsel = j >> 4, off = j & 15;
        int blk = (bsel < 8) ? g_selidx[base + bsel] : ownb;
        int t = blk * 16 + off;
        const float* vr = g_qkv + (size_t)t * QKV_W + DIM_ + 512 + h * DH_;
        float v0 = vr[lane], v1 = vr[lane + 32];
#pragma unroll
        for (int gg = 0; gg < 4; ++gg) {
            float p = sp[wl][gg][j];
            a0[gg] = fmaf(p, v0, a0[gg]);
            a1[gg] = fmaf(p, v1, a1[gg]);
        }
    }
#pragma unroll
    for (int gg = 0; gg < 4; ++gg) {
        float inv = 1.f / sum[gg];
        size_t o = (((size_t)(h * 4 + gg) * S_LEN) + n) * 64;
        g_fout[o + lane]      = a0[gg] * inv;
        g_fout[o + lane + 32] = a1[gg] * inv;
    }
}

// ---------------- sliding-window attention: 4g x 8lane partition ----------
__global__ void slide_kernel()
{
    __shared__ float sp[8][4][66];
    int gw = (blockIdx.x * blockDim.x + threadIdx.x) >> 5;
    int lane = threadIdx.x & 31, wl = (threadIdx.x >> 5) & 7;
    if (gw >= KVH_ * S_LEN) return;
    int h = gw >> 11, n = gw & (S_LEN - 1);
    const int g = lane >> 3, sl = lane & 7;
    const float* qp = g_rq + (((size_t)(h * 4 + g) * S_LEN) + n) * 64 + sl * 8;
    const float4 qa = *(const float4*)qp;
    const float4 qb = *(const float4*)(qp + 4);
    int lo = n - 64; if (lo < 0) lo = 0;
    int cnt = n - lo + 1;

    float mloc = -1e38f;
    for (int jj = 0; jj < cnt; ++jj) {
        const float* kr = g_rk + ((size_t)h * S_LEN + lo + jj) * 64 + sl * 8;
        float4 ka = *(const float4*)kr;
        float4 kb = *(const float4*)(kr + 4);
        float t = qa.x * ka.x + qa.y * ka.y + qa.z * ka.z + qa.w * ka.w
                + qb.x * kb.x + qb.y * kb.y + qb.z * kb.z + qb.w * kb.w;
        t += __shfl_xor_sync(0xffffffffu, t, 1);
        t += __shfl_xor_sync(0xffffffffu, t, 2);
        t += __shfl_xor_sync(0xffffffffu, t, 4);
        float s = t * SCALE_;
        if (sl == 0) sp[wl][g][jj] = s;
        mloc = fmaxf(mloc, s);
    }
    __syncwarp();
    float mg[4];
#pragma unroll
    for (int gg = 0; gg < 4; ++gg) mg[gg] = __shfl_sync(0xffffffffu, mloc, gg * 8);
    float sum[4] = {0.f, 0.f, 0.f, 0.f};
    for (int jj = lane; jj < cnt; jj += 32) {
#pragma unroll
        for (int gg = 0; gg < 4; ++gg) {
            float e = expf(sp[wl][gg][jj] - mg[gg]);
            sp[wl][gg][jj] = e;
            sum[gg] += e;
        }
    }
#pragma unroll
    for (int gg = 0; gg < 4; ++gg)
#pragma unroll
        for (int o = 16; o; o >>= 1) sum[gg] += __shfl_xor_sync(0xffffffffu, sum[gg], o);
    __syncwarp();
    float a0[4] = {0.f, 0.f, 0.f, 0.f}, a1[4] = {0.f, 0.f, 0.f, 0.f};
    for (int jj = 0; jj < cnt; ++jj) {
        const float* vr = g_qkv + (size_t)(lo + jj) * QKV_W + DIM_ + 512 + h * DH_;
        float v0 = vr[lane], v1 = vr[lane + 32];
#pragma unroll
        for (int gg = 0; gg < 4; ++gg) {
            float p = sp[wl][gg][jj];
            a0[gg] = fmaf(p, v0, a0[gg]);
            a1[gg] = fmaf(p, v1, a1[gg]);
        }
    }
#pragma unroll
    for (int gg = 0; gg < 4; ++gg) {
        float inv = 1.f / sum[gg];
        size_t o = (((size_t)(h * 4 + gg) * S_LEN) + n) * 64;
        g_sout[o + lane]      = a0[gg] * inv;
        g_sout[o + lane + 32] = a1[gg] * inv;
    }
}

// ---------------- launcher ----------------
extern "C" void kernel_launch(void* const* d_in, const int* in_sizes, int n_in,
                              void* d_out, int out_size)
{
    const float* x      = (const float*)d_in[0];
    const float* w_qkv  = (const float*)d_in[1];
    const float* k_pos  = (const float*)d_in[2];
    const float* v_pos  = (const float*)d_in[3];
    const float* k_cw1  = (const float*)d_in[4];
    const float* k_cb1  = (const float*)d_in[5];
    const float* k_cw2  = (const float*)d_in[6];
    const float* k_cb2  = (const float*)d_in[7];
    const float* v_cw1  = (const float*)d_in[8];
    const float* v_cb1  = (const float*)d_in[9];
    const float* v_cw2  = (const float*)d_in[10];
    const float* v_cb2  = (const float*)d_in[11];
    const float* mem_ck = (const float*)d_in[12];
    const float* mem_cv = (const float*)d_in[13];
    const float* w_gate = (const float*)d_in[14];
    const float* b_gate = (const float*)d_in[15];
    const float* w_out  = (const float*)d_in[16];
    float* out = (float*)d_out;

    float *qkv, *kbv, *h1, *body, *gate, *ck, *cv;
    cudaGetSymbolAddress((void**)&qkv,  g_qkv);
    cudaGetSymbolAddress((void**)&kbv,  g_kbv);
    cudaGetSymbolAddress((void**)&h1,   g_h1);
    cudaGetSymbolAddress((void**)&body, g_body);
    cudaGetSymbolAddress((void**)&gate, g_gate);
    cudaGetSymbolAddress((void**)&ck,   g_ck);
    cudaGetSymbolAddress((void**)&cv,   g_cv);

    const int NOSPLIT = 1 << 30;

    rope_table<<<(S_LEN * 32) / 256, 256>>>();
    // 1) qkv projection
    split_At<<<dim3(DIM_ / 32, S_LEN / 32), 256>>>(x, S_LEN, DIM_);
    split_B<<<(DIM_ * QKV_W) / 256, 256>>>(w_qkv, 0, QKV_W, DIM_ * QKV_W);
    gemm3p<0><<<PGRID, 128>>>(nullptr, nullptr, qkv, S_LEN, QKV_W, DIM_,
                              768, QKV_W / 64, NOSPLIT, 0);
    // 2) compression inputs
    build_kb_vb<<<(KVH_ * NC_ * CDIM_) / 256, 256>>>(k_pos, v_pos);
    // 3) merged K+V compression MLP layer 1
    split_At<<<dim3(CDIM_ / 32, 2048 / 32), 256>>>(kbv, 2048, CDIM_);
    split_B<<<(CDIM_ * CDIM_) / 256, 256>>>(k_cw1, 0, CDIM_, CDIM_ * CDIM_);
    split_B<<<(CDIM_ * CDIM_) / 256, 256>>>(v_cw1, (size_t)CDIM_ * CDIM_, CDIM_, CDIM_ * CDIM_);
    gemm3p<1><<<256, 128>>>(k_cb1, v_cb1, h1, 2048, CDIM_, CDIM_,
                            256, 16, 8, (size_t)CDIM_ * CDIM_);
    skinny_gemm<0, 64, 4, 4><<<512, 256>>>(h1, k_cw2, v_cw2, k_cb2, v_cb2, body,
                                           64, CDIM_, 1024);
    assemble_c<<<(KVH_ * 129 * DH_ + 255) / 256, 256>>>(mem_ck, ck, body);
    assemble_c<<<(KVH_ * 129 * DH_ + 255) / 256, 256>>>(mem_cv, cv, body + 1024 * 64);
    // 5) compression attention + top-k
    csoft_kernel<<<KVH_ * S_LEN / 8, 256>>>();
    topk_kernel<<<KVH_ * S_LEN / 8, 256>>>();
    // 6) RoPE apply
    rope_apply<<<(40 * S_LEN * 32) / 256, 256>>>();
    // 7) fine + sliding attention
    fine_kernel<<<KVH_ * S_LEN / 8, 256>>>();
    slide_kernel<<<KVH_ * S_LEN / 8, 256>>>();
    // 8) gates
    skinny_gemm<2, 96, 2, 4><<<512, 256>>>(x, w_gate, w_gate, b_gate, b_gate, gate,
                                           96, DIM_, NOSPLIT);
    // 9) fused combine+split, then output projection
    combine_split<<<dim3(DIM_ / 32, S_LEN / 32), 256>>>();
    split_B<<<(DIM_ * DIM_) / 256, 256>>>(w_out, 0, DIM_, DIM_ * DIM_);
    gemm3p<0><<<PGRID, 128>>>(nullptr, nullptr, out, S_LEN, DIM_, DIM_,
                              512, DIM_ / 64, NOSPLIT, 0);
}

// round 17
// speedup vs baseline: 1.1156x; 1.0006x over previous
#include <cuda_runtime.h>
#include <math.h>

// ---------------- problem constants ----------------
#define S_LEN 2048
#define QKV_W 3072
#define DIM_  2048
#define DH_   64
#define KVH_  8
#define HEADS_ 32
#define CDIM_ 1024
#define NC_   128
#define NEGV  (-1e30f)
#define SCALE_ 0.125f
#define PGRID 444

// ---------------- scratch ----------------
__device__ float g_qkv [S_LEN * QKV_W];
__device__ float g_kbv [2 * KVH_ * NC_ * CDIM_];
__device__ float g_h1  [2 * KVH_ * NC_ * CDIM_];
__device__ float g_body[2 * KVH_ * NC_ * DH_];
__device__ float g_ck  [KVH_ * 129 * DH_];
__device__ float g_cv  [KVH_ * 129 * DH_];
__device__ float g_cout[HEADS_ * S_LEN * DH_];
__device__ float g_fout[HEADS_ * S_LEN * DH_];
__device__ float g_sout[HEADS_ * S_LEN * DH_];
__device__ float g_rq  [HEADS_ * S_LEN * DH_];
__device__ float g_rk  [KVH_  * S_LEN * DH_];
__device__ float g_rcs [S_LEN * 32 * 2];
__device__ int           g_selidx [KVH_ * S_LEN * 8];
__device__ unsigned char g_selmask[KVH_ * S_LEN * 8];
__device__ float g_gate[S_LEN * 96];
// split operand scratch (fragment-interleaved layouts)
__device__ unsigned g_Ahi[DIM_ * S_LEN];
__device__ unsigned g_Alo[DIM_ * S_LEN];
__device__ unsigned g_Bhi[DIM_ * QKV_W];
__device__ unsigned g_Blo[DIM_ * QKV_W];

__device__ __forceinline__ int pB_(int n) { return (n & ~31) + ((n & 7) << 2) + ((n >> 3) & 3); }

// ================= split helpers =================
__device__ __forceinline__ unsigned f2tf(float x)
{
    unsigned r;
    asm("cvt.rna.tf32.f32 %0, %1;" : "=r"(r) : "f"(x));
    return r;
}

__device__ __forceinline__ void split_tf(float x, unsigned& hi, unsigned& lo)
{
    hi = f2tf(x);
    lo = f2tf(x - __uint_as_float(hi));
}

__device__ __forceinline__ void mma_tf32(float* c, const unsigned* a, const unsigned* b)
{
    asm volatile(
        "mma.sync.aligned.m16n8k8.row.col.f32.tf32.tf32.f32 "
        "{%0,%1,%2,%3}, {%4,%5,%6,%7}, {%8,%9}, {%0,%1,%2,%3};"
        : "+f"(c[0]), "+f"(c[1]), "+f"(c[2]), "+f"(c[3])
        : "r"(a[0]), "r"(a[1]), "r"(a[2]), "r"(a[3]), "r"(b[0]), "r"(b[1]));
}

__device__ __forceinline__ void cp16(unsigned saddr, const void* g)
{
    asm volatile("cp.async.ca.shared.global [%0], [%1], 16;" :: "r"(saddr), "l"(g));
}

// split + transpose A
__global__ void split_At(const float* __restrict__ A, int M, int K)
{
    __shared__ float t[32][33];
    const int tid = threadIdx.x;
    const int k0 = blockIdx.x * 32, m0 = blockIdx.y * 32;
    const int c = tid & 31, r = tid >> 5;
#pragma unroll
    for (int i = r; i < 32; i += 8)
        t[i][c] = A[(size_t)(m0 + i) * K + k0 + c];
    __syncthreads();
#pragma unroll
    for (int i = r; i < 32; i += 8) {
        unsigned hi, lo;
        split_tf(t[c][i], hi, lo);
        size_t o = (size_t)(k0 + i) * M + m0 + ((c & 16) + ((c & 7) << 1) + ((c >> 3) & 1));
        g_Ahi[o] = hi;
        g_Alo[o] = lo;
    }
}

// split B
__global__ void split_B(const float* __restrict__ B, size_t off, int N, int total)
{
    int idx = blockIdx.x * blockDim.x + threadIdx.x;
    if (idx >= total) return;
    int n = idx % N, k = idx / N;
    unsigned hi, lo;
    split_tf(B[idx], hi, lo);
    size_t o = off + (size_t)k * N + pB_(n);
    g_Bhi[o] = hi;
    g_Blo[o] = lo;
}

// fused gated-combine + split + transpose
__global__ void combine_split(void)
{
    __shared__ float t[32][33];
    const int tid = threadIdx.x;
    const int c0 = blockIdx.x * 32;
    const int n0 = blockIdx.y * 32;
    const int c = tid & 31, r = tid >> 5;
    const int hg = c0 >> 6;
#pragma unroll
    for (int i = r; i < 32; i += 8) {
        int n = n0 + i;
        float gg0 = g_gate[n * 96 + hg * 3];
        float gg1 = g_gate[n * 96 + hg * 3 + 1];
        float gg2 = g_gate[n * 96 + hg * 3 + 2];
        size_t src = ((size_t)hg * S_LEN + n) * 64 + ((c0 + c) & 63);
        t[i][c] = gg0 * g_cout[src] + gg1 * g_fout[src] + gg2 * g_sout[src];
    }
    __syncthreads();
#pragma unroll
    for (int i = r; i < 32; i += 8) {
        unsigned hi, lo;
        split_tf(t[c][i], hi, lo);
        size_t o = (size_t)(c0 + i) * DIM_ + n0 + ((c & 16) + ((c & 7) << 1) + ((c >> 3) & 1));
        g_Ahi[o] = hi;
        g_Alo[o] = lo;
    }
}

// ================= 3-product TF32 GEMM, persistent grid-strided ============
template <int ACT>
__global__ void __launch_bounds__(128, 3)
gemm3p(const float* __restrict__ bias0, const float* __restrict__ bias1,
       float* __restrict__ C, int M, int N, int K,
       int ntiles, int bxdim, int bysplit, size_t boff)
{
    __shared__ __align__(16) unsigned Ah[3][8][136], Al[3][8][136];
    __shared__ __align__(16) unsigned Bh[3][8][72],  Bl[3][8][72];
    const int tid = threadIdx.x;
    const int lane = tid & 31;
    const int wid = tid >> 5;
    const int wm = wid * 32;

    const int ar0 = tid >> 5;
    const int ac0 = (tid & 31) << 2;
    const int ar1 = (tid + 128) >> 5;
    const int brow = tid >> 4;
    const int bc4  = (tid & 15) << 2;

    const unsigned sAh = (unsigned)__cvta_generic_to_shared(&Ah[0][0][0]);
    const unsigned sAl = (unsigned)__cvta_generic_to_shared(&Al[0][0][0]);
    const unsigned sBh = (unsigned)__cvta_generic_to_shared(&Bh[0][0][0]);
    const unsigned sBl = (unsigned)__cvta_generic_to_shared(&Bl[0][0][0]);
    const unsigned aoff0 = (unsigned)(ar0 * 136 + ac0) * 4u;
    const unsigned aoff1 = (unsigned)(ar1 * 136 + ac0) * 4u;
    const unsigned boffs = (unsigned)(brow * 72 + bc4) * 4u;

    const int rr = lane >> 2;
    const int lc = lane & 3;
    const int k0 = lc, k1 = lc + 4;
    const int ktiles = K >> 3;

    for (int tile = blockIdx.x; tile < ntiles; tile += gridDim.x) {
        const int bx = tile % bxdim;
        const int by = tile / bxdim;
        const bool second = (by >= bysplit);
        const size_t bofs = second ? boff : 0;
        const float* bias = second ? bias1 : bias0;
        const size_t abase = (size_t)by * 128;
        const size_t bbase = (size_t)bx * 64;

        __syncthreads();

#define ISSUE_(s, kt) do {                                                   \
        size_t a0_ = (size_t)((kt) * 8 + ar0) * M + abase + ac0;             \
        size_t a1_ = (size_t)((kt) * 8 + ar1) * M + abase + ac0;             \
        cp16(sAh + (unsigned)(s) * 4352u + aoff0, g_Ahi + a0_);              \
        cp16(sAh + (unsigned)(s) * 4352u + aoff1, g_Ahi + a1_);              \
        cp16(sAl + (unsigned)(s) * 4352u + aoff0, g_Alo + a0_);              \
        cp16(sAl + (unsigned)(s) * 4352u + aoff1, g_Alo + a1_);              \
        size_t bo_ = bofs + (size_t)((kt) * 8 + brow) * N + bbase + bc4;     \
        cp16(sBh + (unsigned)(s) * 2304u + boffs, g_Bhi + bo_);              \
        cp16(sBl + (unsigned)(s) * 2304u + boffs, g_Blo + bo_);              \
        asm volatile("cp.async.commit_group;" ::: "memory");                 \
    } while (0)

        ISSUE_(0, 0);
        ISSUE_(1, 1);

        float acc[2][8][4];
#pragma unroll
        for (int mf = 0; mf < 2; ++mf)
#pragma unroll
            for (int nf = 0; nf < 8; ++nf)
#pragma unroll
                for (int i = 0; i < 4; ++i) acc[mf][nf][i] = 0.f;

        int cur = 0;
        for (int kt = 0; kt < ktiles; ++kt) {
            asm volatile("cp.async.wait_group 1;" ::: "memory");
            __syncthreads();

            const unsigned* pAh = &Ah[cur][0][0];
            const unsigned* pAl = &Al[cur][0][0];
            const unsigned* pBh = &Bh[cur][0][0];
            const unsigned* pBl = &Bl[cur][0][0];
            const int wa0 = k0 * 136 + wm + 2 * rr;
            const int wa1 = k1 * 136 + wm + 2 * rr;
            const int wb0 = k0 * 72 + 4 * rr;
            const int wb1 = k1 * 72 + 4 * rr;

            unsigned bh[8][2], bl[8][2];
            {
                uint4 h0 = *(const uint4*)(pBh + wb0);
                uint4 h1 = *(const uint4*)(pBh + wb1);
                uint4 h2 = *(const uint4*)(pBh + wb0 + 32);
                uint4 h3 = *(const uint4*)(pBh + wb1 + 32);
                uint4 l0 = *(const uint4*)(pBl + wb0);
                uint4 l1 = *(const uint4*)(pBl + wb1);
                uint4 l2 = *(const uint4*)(pBl + wb0 + 32);
                uint4 l3 = *(const uint4*)(pBl + wb1 + 32);
                bh[0][0] = h0.x; bh[1][0] = h0.y; bh[2][0] = h0.z; bh[3][0] = h0.w;
                bh[0][1] = h1.x; bh[1][1] = h1.y; bh[2][1] = h1.z; bh[3][1] = h1.w;
                bh[4][0] = h2.x; bh[5][0] = h2.y; bh[6][0] = h2.z; bh[7][0] = h2.w;
                bh[4][1] = h3.x; bh[5][1] = h3.y; bh[6][1] = h3.z; bh[7][1] = h3.w;
                bl[0][0] = l0.x; bl[1][0] = l0.y; bl[2][0] = l0.z; bl[3][0] = l0.w;
                bl[0][1] = l1.x; bl[1][1] = l1.y; bl[2][1] = l1.z; bl[3][1] = l1.w;
                bl[4][0] = l2.x; bl[5][0] = l2.y; bl[6][0] = l2.z; bl[7][0] = l2.w;
                bl[4][1] = l3.x; bl[5][1] = l3.y; bl[6][1] = l3.z; bl[7][1] = l3.w;
            }
            unsigned ah[2][4], al[2][4];
#pragma unroll
            for (int mf = 0; mf < 2; ++mf) {
                uint2 h0 = *(const uint2*)(pAh + wa0 + mf * 16);
                uint2 h1 = *(const uint2*)(pAh + wa1 + mf * 16);
                uint2 l0 = *(const uint2*)(pAl + wa0 + mf * 16);
                uint2 l1 = *(const uint2*)(pAl + wa1 + mf * 16);
                ah[mf][0] = h0.x; ah[mf][1] = h0.y; ah[mf][2] = h1.x; ah[mf][3] = h1.y;
                al[mf][0] = l0.x; al[mf][1] = l0.y; al[mf][2] = l1.x; al[mf][3] = l1.y;
            }
#pragma unroll
            for (int mf = 0; mf < 2; ++mf)
#pragma unroll
                for (int nf = 0; nf < 8; ++nf)
                    mma_tf32(acc[mf][nf], al[mf], bh[nf]);
#pragma unroll
            for (int mf = 0; mf < 2; ++mf)
#pragma unroll
                for (int nf = 0; nf < 8; ++nf)
                    mma_tf32(acc[mf][nf], ah[mf], bl[nf]);
#pragma unroll
            for (int mf = 0; mf < 2; ++mf)
#pragma unroll
                for (int nf = 0; nf < 8; ++nf)
                    mma_tf32(acc[mf][nf], ah[mf], bh[nf]);

            if (kt + 2 < ktiles) {
                int s = (cur + 2) % 3;
                ISSUE_(s, kt + 2);
            } else {
                asm volatile("cp.async.commit_group;" ::: "memory");
            }
            cur = (cur + 1) % 3;
        }
#undef ISSUE_

        const int cc2 = lc * 2;
#pragma unroll
        for (int mf = 0; mf < 2; ++mf) {
            const int r0 = by * 128 + wm + mf * 16 + rr;
#pragma unroll
            for (int nf = 0; nf < 8; ++nf) {
                const int col = bx * 64 + nf * 8 + cc2;
                float b0 = bias ? bias[col] : 0.f;
                float b1 = bias ? bias[col + 1] : 0.f;
                float v0 = acc[mf][nf][0] + b0, v1 = acc[mf][nf][1] + b1;
                float v2 = acc[mf][nf][2] + b0, v3 = acc[mf][nf][3] + b1;
                if (ACT == 1) {
                    v0 = fmaxf(v0, 0.f); v1 = fmaxf(v1, 0.f);
                    v2 = fmaxf(v2, 0.f); v3 = fmaxf(v3, 0.f);
                }
                float2 w0 = {v0, v1}, w1 = {v2, v3};
                *(float2*)(C + (size_t)r0 * N + col) = w0;
                *(float2*)(C + (size_t)(r0 + 8) * N + col) = w1;
            }
        }
    }
}

// ================= skinny GEMM with row-split B select ==========
template <int ACT, int NCOL, int NSL, int RPB>
__global__ void skinny_gemm(const float* __restrict__ A, const float* __restrict__ B,
                            const float* __restrict__ B2, const float* __restrict__ bias,
                            const float* __restrict__ bias2, float* __restrict__ C,
                            int N, int K, int rowsplit)
{
    __shared__ float sA[RPB][128];
    __shared__ float sred[NSL][RPB][NCOL];
    const int tid = threadIdx.x;
    const int row0 = blockIdx.x * RPB;
    if (row0 >= rowsplit) { B = B2; bias = bias2; }
    const int c = tid % NCOL, sl = tid / NCOL;
    const bool active = sl < NSL;
    const int kper = 128 / NSL;
    float acc[RPB];
#pragma unroll
    for (int r = 0; r < RPB; ++r) acc[r] = 0.f;

    for (int k0 = 0; k0 < K; k0 += 128) {
        __syncthreads();
        for (int i = tid; i < RPB * 128; i += 256) {
            int r = i >> 7, kk = i & 127;
            sA[r][kk] = A[(size_t)(row0 + r) * K + k0 + kk];
        }
        __syncthreads();
        if (active) {
            for (int kk = sl * kper; kk < (sl + 1) * kper; ++kk) {
                float b = B[(size_t)(k0 + kk) * N + c];
#pragma unroll
                for (int r = 0; r < RPB; ++r) acc[r] = fmaf(sA[r][kk], b, acc[r]);
            }
        }
    }
    if (active) {
#pragma unroll
        for (int r = 0; r < RPB; ++r) sred[sl][r][c] = acc[r];
    }
    __syncthreads();
    for (int i = tid; i < RPB * NCOL; i += 256) {
        int r = i / NCOL, cc = i % NCOL;
        float s = 0.f;
#pragma unroll
        for (int q = 0; q < NSL; ++q) s += sred[q][r][cc];
        if (bias) s += bias[cc];
        if (ACT == 2) s = 1.f / (1.f + expf(-s));
        C[(size_t)(row0 + r) * N + cc] = s;
    }
}

// ---------------- kb/vb construction ----------------
__global__ void build_kb_vb(const float* __restrict__ k_pos, const float* __restrict__ v_pos)
{
    int idx = blockIdx.x * blockDim.x + threadIdx.x;
    if (idx >= KVH_ * NC_ * CDIM_) return;
    int d = idx & 63;
    int i = (idx >> 6) & 15;
    int c = (idx >> 10) & 127;
    int h = idx >> 17;
    int t = c * 16 + i;
    float kv = g_qkv[(size_t)t * QKV_W + DIM_ + h * DH_ + d];
    float vv = g_qkv[(size_t)t * QKV_W + DIM_ + 512 + h * DH_ + d];
    g_kbv[idx]                      = kv + k_pos[(h * 16 + i) * 64 + d];
    g_kbv[idx + KVH_ * NC_ * CDIM_] = vv + v_pos[(h * 16 + i) * 64 + d];
}

// ---------------- assemble ck+cv (merged) ----------------
__global__ void assemble_c2(const float* __restrict__ mem_ck, const float* __restrict__ mem_cv)
{
    int idx = blockIdx.x * blockDim.x + threadIdx.x;
    if (idx >= 2 * KVH_ * 129 * DH_) return;
    int half = idx >= KVH_ * 129 * DH_;
    int id = idx - half * (KVH_ * 129 * DH_);
    int d = id % 64;
    int j = (id / 64) % 129;
    int h = id / (64 * 129);
    const float* mem  = half ? mem_cv : mem_ck;
    const float* body = g_body + half * (1024 * 64);
    float* dst        = half ? g_cv : g_ck;
    dst[id] = (j == 0) ? mem[h * 64 + d] : body[((h * NC_) + (j - 1)) * 64 + d];
}

// ---------------- compression attention + fused top-8 ----------------------
__global__ void csoft_kernel()
{
    __shared__ float sp[8][4][132];
    int gw = (blockIdx.x * blockDim.x + threadIdx.x) >> 5;
    int lane = threadIdx.x & 31, wl = (threadIdx.x >> 5) & 7;
    if (gw >= KVH_ * S_LEN) return;
    int h = gw >> 11, n = gw & (S_LEN - 1);
    const int g = lane >> 3, sl = lane & 7;
    const float* qp = g_qkv + (size_t)n * QKV_W + h * 4 * DH_ + g * 64 + sl * 8;
    const float4 qa = *(const float4*)qp;
    const float4 qb = *(const float4*)(qp + 4);
    const float* ckh = g_ck + h * 129 * 64;
    const int nvalid = (n >> 4) + 1;

    float mloc = -1e38f;
    for (int j = 0; j < nvalid; ++j) {
        const float* kr = ckh + j * 64 + sl * 8;
        float4 ka = *(const float4*)kr;
        float4 kb = *(const float4*)(kr + 4);
        float t = qa.x * ka.x + qa.y * ka.y + qa.z * ka.z + qa.w * ka.w
                + qb.x * kb.x + qb.y * kb.y + qb.z * kb.z + qb.w * kb.w;
        t += __shfl_xor_sync(0xffffffffu, t, 1);
        t += __shfl_xor_sync(0xffffffffu, t, 2);
        t += __shfl_xor_sync(0xffffffffu, t, 4);
        float s = t * SCALE_;
        if (sl == 0) sp[wl][g][j] = s;
        mloc = fmaxf(mloc, s);
    }
    __syncwarp();
    float mg[4];
#pragma unroll
    for (int gg = 0; gg < 4; ++gg) mg[gg] = __shfl_sync(0xffffffffu, mloc, gg * 8);

    // ---- fused top-8 selection (bitwise-identical to old topk_kernel) ----
    {
        float vals[4];
        int js[4];
#pragma unroll
        for (int r = 0; r < 4; ++r) {
            int jj = lane + r * 32;            // block index 0..127, sim j = jj+1
            float s = 0.f;
#pragma unroll
            for (int gg = 0; gg < 4; ++gg)
                s += (jj + 1 < nvalid) ? sp[wl][gg][jj + 1] : NEGV;
            vals[r] = s * 0.25f;
            js[r] = jj;
        }
        float m = -1000.f;
#pragma unroll
        for (int r = 0; r < 4; ++r) m = fmaxf(m, vals[r]);
#pragma unroll
        for (int o = 16; o; o >>= 1) m = fmaxf(m, __shfl_xor_sync(0xffffffffu, m, o));
        float sum = 0.f;
#pragma unroll
        for (int r = 0; r < 4; ++r) sum += expf(vals[r] - m);
#pragma unroll
        for (int o = 16; o; o >>= 1) sum += __shfl_xor_sync(0xffffffffu, sum, o);
        sum += expf(-1000.f - m);
        for (int t = 0; t < 8; ++t) {
            float bv = vals[0]; int bj = js[0];
#pragma unroll
            for (int r = 1; r < 4; ++r)
                if (vals[r] > bv || (vals[r] == bv && js[r] < bj)) { bv = vals[r]; bj = js[r]; }
            float v = bv; int j = bj;
#pragma unroll
            for (int o = 16; o; o >>= 1) {
                float vo = __shfl_xor_sync(0xffffffffu, v, o);
                int   jo = __shfl_xor_sync(0xffffffffu, j, o);
                if (vo > v || (vo == v && jo < j)) { v = vo; j = jo; }
            }
            if (lane == 0) {
                g_selidx[gw * 8 + t] = j;
                float p = expf(v - m) / sum;
                g_selmask[gw * 8 + t] = (p > 1e-10f) ? 1 : 0;
            }
            int owner = j & 31, rr2 = j >> 5;
            if (lane == owner) vals[rr2] = -INFINITY;
        }
    }

    // ---- softmax + V (unchanged) ----
    float sum[4] = {0.f, 0.f, 0.f, 0.f};
    for (int j = lane; j < nvalid; j += 32) {
#pragma unroll
        for (int gg = 0; gg < 4; ++gg) {
            float e = expf(sp[wl][gg][j] - mg[gg]);
            sp[wl][gg][j] = e;
            sum[gg] += e;
        }
    }
#pragma unroll
    for (int gg = 0; gg < 4; ++gg)
#pragma unroll
        for (int o = 16; o; o >>= 1) sum[gg] += __shfl_xor_sync(0xffffffffu, sum[gg], o);
    __syncwarp();
    const float* cvh = g_cv + h * 129 * 64;
    float a0[4] = {0.f, 0.f, 0.f, 0.f}, a1[4] = {0.f, 0.f, 0.f, 0.f};
    for (int j = 0; j < nvalid; ++j) {
        float v0 = cvh[j * 64 + lane], v1 = cvh[j * 64 + lane + 32];
#pragma unroll
        for (int gg = 0; gg < 4; ++gg) {
            float p = sp[wl][gg][j];
            a0[gg] = fmaf(p, v0, a0[gg]);
            a1[gg] = fmaf(p, v1, a1[gg]);
        }
    }
#pragma unroll
    for (int gg = 0; gg < 4; ++gg) {
        float inv = 1.f / sum[gg];
        size_t o = (((size_t)(h * 4 + gg) * S_LEN) + n) * 64;
        g_cout[o + lane]      = a0[gg] * inv;
        g_cout[o + lane + 32] = a1[gg] * inv;
    }
}

// ---------------- RoPE ----------------
__global__ void rope_table()
{
    int idx = blockIdx.x * blockDim.x + threadIdx.x;
    if (idx >= S_LEN * 32) return;
    int p = idx & 31;
    int n = idx >> 5;
    double inv = pow(10000.0, -((double)(2 * p)) / 64.0);
    double a = (double)n * inv;
    g_rcs[idx * 2]     = (float)cos(a);
    g_rcs[idx * 2 + 1] = (float)sin(a);
}

__global__ void rope_apply()
{
    int idx = blockIdx.x * blockDim.x + threadIdx.x;
    if (idx >= 40 * S_LEN * 32) return;
    int p = idx & 31;
    int n = (idx >> 5) & (S_LEN - 1);
    int hh = idx >> 16;
    float c = g_rcs[(n * 32 + p) * 2];
    float s = g_rcs[(n * 32 + p) * 2 + 1];
    const float* src; float* dst;
    if (hh < 32) {
        src = g_qkv + (size_t)n * QKV_W + hh * DH_;
        dst = g_rq + ((size_t)hh * S_LEN + n) * DH_;
    } else {
        int h = hh - 32;
        src = g_qkv + (size_t)n * QKV_W + DIM_ + h * DH_;
        dst = g_rk + ((size_t)h * S_LEN + n) * DH_;
    }
    float x1 = src[2 * p], x2 = src[2 * p + 1];
    dst[2 * p]     = x1 * c - x2 * s;
    dst[2 * p + 1] = x1 * s + x2 * c;
}

// ---------------- fine attention: 4g x 8lane partition (sim pass) ----------
__global__ void fine_kernel()
{
    __shared__ float sp[8][4][144];
    int gw = (blockIdx.x * blockDim.x + threadIdx.x) >> 5;
    int lane = threadIdx.x & 31, wl = (threadIdx.x >> 5) & 7;
    if (gw >= KVH_ * S_LEN) return;
    int h = gw >> 11, n = gw & (S_LEN - 1);
    const int g = lane >> 3, sl = lane & 7;
    const float* qp = g_rq + (((size_t)(h * 4 + g) * S_LEN) + n) * 64 + sl * 8;
    const float4 qa = *(const float4*)qp;
    const float4 qb = *(const float4*)(qp + 4);
    const int base = (h * S_LEN + n) * 8;
    const int ownb = n >> 4;

    float mloc = -1e38f;
    for (int j = 0; j < 144; ++j) {
        int bsel = j >> 4, off = j & 15;
        int blk; bool valid;
        if (bsel < 8) { blk = g_selidx[base + bsel]; valid = g_selmask[base + bsel] != 0; }
        else          { blk = ownb;                  valid = (n & 15) >= off; }
        float s = NEGV;
        if (valid) {
            const float* kr = g_rk + ((size_t)h * S_LEN + blk * 16 + off) * 64 + sl * 8;
            float4 ka = *(const float4*)kr;
            float4 kb = *(const float4*)(kr + 4);
            float t = qa.x * ka.x + qa.y * ka.y + qa.z * ka.z + qa.w * ka.w
                    + qb.x * kb.x + qb.y * kb.y + qb.z * kb.z + qb.w * kb.w;
            t += __shfl_xor_sync(0xffffffffu, t, 1);
            t += __shfl_xor_sync(0xffffffffu, t, 2);
            t += __shfl_xor_sync(0xffffffffu, t, 4);
            s = t * SCALE_;
        }
        if (sl == 0) sp[wl][g][j] = s;
        mloc = fmaxf(mloc, s);
    }
    __syncwarp();
    float mg[4];
#pragma unroll
    for (int gg = 0; gg < 4; ++gg) mg[gg] = __shfl_sync(0xffffffffu, mloc, gg * 8);
    float sum[4] = {0.f, 0.f, 0.f, 0.f};
    for (int j = lane; j < 144; j += 32) {
#pragma unroll
        for (int gg = 0; gg < 4; ++gg) {
            float e = expf(sp[wl][gg][j] - mg[gg]);
            sp[wl][gg][j] = e;
            sum[gg] += e;
        }
    }
#pragma unroll
    for (int gg = 0; gg < 4; ++gg)
#pragma unroll
        for (int o = 16; o; o >>= 1) sum[gg] += __shfl_xor_sync(0xffffffffu, sum[gg], o);
    __syncwarp();
    float a0[4] = {0.f, 0.f, 0.f, 0.f}, a1[4] = {0.f, 0.f, 0.f, 0.f};
    for (int j = 0; j < 144; ++j) {
        int bsel = j >> 4, off = j & 15;
        int blk = (bsel < 8) ? g_selidx[base + bsel] : ownb;
        int t = blk * 16 + off;
        const float* vr = g_qkv + (size_t)t * QKV_W + DIM_ + 512 + h * DH_;
        float v0 = vr[lane], v1 = vr[lane + 32];
#pragma unroll
        for (int gg = 0; gg < 4; ++gg) {
            float p = sp[wl][gg][j];
            a0[gg] = fmaf(p, v0, a0[gg]);
            a1[gg] = fmaf(p, v1, a1[gg]);
        }
    }
#pragma unroll
    for (int gg = 0; gg < 4; ++gg) {
        float inv = 1.f / sum[gg];
        size_t o = (((size_t)(h * 4 + gg) * S_LEN) + n) * 64;
        g_fout[o + lane]      = a0[gg] * inv;
        g_fout[o + lane + 32] = a1[gg] * inv;
    }
}

// ---------------- sliding-window attention: 4g x 8lane partition ----------
__global__ void slide_kernel()
{
    __shared__ float sp[8][4][66];
    int gw = (blockIdx.x * blockDim.x + threadIdx.x) >> 5;
    int lane = threadIdx.x & 31, wl = (threadIdx.x >> 5) & 7;
    if (gw >= KVH_ * S_LEN) return;
    int h = gw >> 11, n = gw & (S_LEN - 1);
    const int g = lane >> 3, sl = lane & 7;
    const float* qp = g_rq + (((size_t)(h * 4 + g) * S_LEN) + n) * 64 + sl * 8;
    const float4 qa = *(const float4*)qp;
    const float4 qb = *(const float4*)(qp + 4);
    int lo = n - 64; if (lo < 0) lo = 0;
    int cnt = n - lo + 1;

    float mloc = -1e38f;
    for (int jj = 0; jj < cnt; ++jj) {
        const float* kr = g_rk + ((size_t)h * S_LEN + lo + jj) * 64 + sl * 8;
        float4 ka = *(const float4*)kr;
        float4 kb = *(const float4*)(kr + 4);
        float t = qa.x * ka.x + qa.y * ka.y + qa.z * ka.z + qa.w * ka.w
                + qb.x * kb.x + qb.y * kb.y + qb.z * kb.z + qb.w * kb.w;
        t += __shfl_xor_sync(0xffffffffu, t, 1);
        t += __shfl_xor_sync(0xffffffffu, t, 2);
        t += __shfl_xor_sync(0xffffffffu, t, 4);
        float s = t * SCALE_;
        if (sl == 0) sp[wl][g][jj] = s;
        mloc = fmaxf(mloc, s);
    }
    __syncwarp();
    float mg[4];
#pragma unroll
    for (int gg = 0; gg < 4; ++gg) mg[gg] = __shfl_sync(0xffffffffu, mloc, gg * 8);
    float sum[4] = {0.f, 0.f, 0.f, 0.f};
    for (int jj = lane; jj < cnt; jj += 32) {
#pragma unroll
        for (int gg = 0; gg < 4; ++gg) {
            float e = expf(sp[wl][gg][jj] - mg[gg]);
            sp[wl][gg][jj] = e;
            sum[gg] += e;
        }
    }
#pragma unroll
    for (int gg = 0; gg < 4; ++gg)
#pragma unroll
        for (int o = 16; o; o >>= 1) sum[gg] += __shfl_xor_sync(0xffffffffu, sum[gg], o);
    __syncwarp();
    float a0[4] = {0.f, 0.f, 0.f, 0.f}, a1[4] = {0.f, 0.f, 0.f, 0.f};
    for (int jj = 0; jj < cnt; ++jj) {
        const float* vr = g_qkv + (size_t)(lo + jj) * QKV_W + DIM_ + 512 + h * DH_;
        float v0 = vr[lane], v1 = vr[lane + 32];
#pragma unroll
        for (int gg = 0; gg < 4; ++gg) {
            float p = sp[wl][gg][jj];
            a0[gg] = fmaf(p, v0, a0[gg]);
            a1[gg] = fmaf(p, v1, a1[gg]);
        }
    }
#pragma unroll
    for (int gg = 0; gg < 4; ++gg) {
        float inv = 1.f / sum[gg];
        size_t o = (((size_t)(h * 4 + gg) * S_LEN) + n) * 64;
        g_sout[o + lane]      = a0[gg] * inv;
        g_sout[o + lane + 32] = a1[gg] * inv;
    }
}

// ---------------- launcher ----------------
extern "C" void kernel_launch(void* const* d_in, const int* in_sizes, int n_in,
                              void* d_out, int out_size)
{
    const float* x      = (const float*)d_in[0];
    const float* w_qkv  = (const float*)d_in[1];
    const float* k_pos  = (const float*)d_in[2];
    const float* v_pos  = (const float*)d_in[3];
    const float* k_cw1  = (const float*)d_in[4];
    const float* k_cb1  = (const float*)d_in[5];
    const float* k_cw2  = (const float*)d_in[6];
    const float* k_cb2  = (const float*)d_in[7];
    const float* v_cw1  = (const float*)d_in[8];
    const float* v_cb1  = (const float*)d_in[9];
    const float* v_cw2  = (const float*)d_in[10];
    const float* v_cb2  = (const float*)d_in[11];
    const float* mem_ck = (const float*)d_in[12];
    const float* mem_cv = (const float*)d_in[13];
    const float* w_gate = (const float*)d_in[14];
    const float* b_gate = (const float*)d_in[15];
    const float* w_out  = (const float*)d_in[16];
    float* out = (float*)d_out;

    float *qkv, *kbv, *h1, *body, *gate;
    cudaGetSymbolAddress((void**)&qkv,  g_qkv);
    cudaGetSymbolAddress((void**)&kbv,  g_kbv);
    cudaGetSymbolAddress((void**)&h1,   g_h1);
    cudaGetSymbolAddress((void**)&body, g_body);
    cudaGetSymbolAddress((void**)&gate, g_gate);

    const int NOSPLIT = 1 << 30;

    rope_table<<<(S_LEN * 32) / 256, 256>>>();
    // 1) qkv projection
    split_At<<<dim3(DIM_ / 32, S_LEN / 32), 256>>>(x, S_LEN, DIM_);
    split_B<<<(DIM_ * QKV_W) / 256, 256>>>(w_qkv, 0, QKV_W, DIM_ * QKV_W);
    gemm3p<0><<<PGRID, 128>>>(nullptr, nullptr, qkv, S_LEN, QKV_W, DIM_,
                              768, QKV_W / 64, NOSPLIT, 0);
    // 2) compression inputs
    build_kb_vb<<<(KVH_ * NC_ * CDIM_) / 256, 256>>>(k_pos, v_pos);
    // 3) merged K+V compression MLP layer 1
    split_At<<<dim3(CDIM_ / 32, 2048 / 32), 256>>>(kbv, 2048, CDIM_);
    split_B<<<(CDIM_ * CDIM_) / 256, 256>>>(k_cw1, 0, CDIM_, CDIM_ * CDIM_);
    split_B<<<(CDIM_ * CDIM_) / 256, 256>>>(v_cw1, (size_t)CDIM_ * CDIM_, CDIM_, CDIM_ * CDIM_);
    gemm3p<1><<<256, 128>>>(k_cb1, v_cb1, h1, 2048, CDIM_, CDIM_,
                            256, 16, 8, (size_t)CDIM_ * CDIM_);
    skinny_gemm<0, 64, 4, 4><<<512, 256>>>(h1, k_cw2, v_cw2, k_cb2, v_cb2, body,
                                           64, CDIM_, 1024);
    assemble_c2<<<(2 * KVH_ * 129 * DH_ + 255) / 256, 256>>>(mem_ck, mem_cv);
    // 5) compression attention with fused top-k
    csoft_kernel<<<KVH_ * S_LEN / 8, 256>>>();
    // 6) RoPE apply
    rope_apply<<<(40 * S_LEN * 32) / 256, 256>>>();
    // 7) fine + sliding attention
    fine_kernel<<<KVH_ * S_LEN / 8, 256>>>();
    slide_kernel<<<KVH_ * S_LEN / 8, 256>>>();
    // 8) gates
    skinny_gemm<2, 96, 2, 4><<<512, 256>>>(x, w_gate, w_gate, b_gate, b_gate, gate,
                                           96, DIM_, NOSPLIT);
    // 9) fused combine+split, then output projection
    combine_split<<<dim3(DIM_ / 32, S_LEN / 32), 256>>>();
    split_B<<<(DIM_ * DIM_) / 256, 256>>>(w_out, 0, DIM_, DIM_ * DIM_);
    gemm3p<0><<<PGRID, 128>>>(nullptr, nullptr, out, S_LEN, DIM_, DIM_,
                              512, DIM_ / 64, NOSPLIT, 0);
}